// round 1
// baseline (speedup 1.0000x reference)
#include <cuda_runtime.h>
#include <cuda_bf16.h>
#include <math.h>

#define D 128
#define H 8
#define DH 16
#define NMAX 100000
#define EMAX 1600000
#define RMAX 128
#define ALPHA 0.1f

// ---------------- scratch (device globals; no allocations) ----------------
__device__ float d_xn[NMAX * D];
__device__ float d_k[NMAX * D];
__device__ float d_q[NMAX * D];
__device__ float d_v[NMAX * D];
__device__ float d_featA[NMAX * D];
__device__ float d_featB[NMAX * D];
__device__ float d_ex[EMAX * H];
__device__ float d_relx[RMAX * D];
__device__ float d_relp[RMAX * D];
__device__ int   d_deg[NMAX];
__device__ int   d_rowoff[NMAX];
__device__ int   d_cursor[NMAX];
__device__ int   d_srcs[EMAX];
__device__ int   d_rids[EMAX];
__device__ int   d_bsums[256];

// ---------------- CSR build ----------------
__global__ void zero_deg_kernel(int* deg, int n) {
    int i = blockIdx.x * blockDim.x + threadIdx.x;
    if (i < n) deg[i] = 0;
}

__global__ void hist_kernel(const int* __restrict__ dst, int* deg, int E) {
    int e = blockIdx.x * blockDim.x + threadIdx.x;
    if (e < E) atomicAdd(&deg[dst[e]], 1);
}

__global__ void scan1_kernel(const int* __restrict__ deg, int* rowoff, int* bsums, int n) {
    __shared__ int sh[1024];
    int i = blockIdx.x * 1024 + threadIdx.x;
    int v = (i < n) ? deg[i] : 0;
    sh[threadIdx.x] = v;
    __syncthreads();
    for (int off = 1; off < 1024; off <<= 1) {
        int t = (threadIdx.x >= off) ? sh[threadIdx.x - off] : 0;
        __syncthreads();
        sh[threadIdx.x] += t;
        __syncthreads();
    }
    if (i < n) rowoff[i] = sh[threadIdx.x] - v;  // exclusive
    if (threadIdx.x == 1023) bsums[blockIdx.x] = sh[1023];
}

__global__ void scan2_kernel(int* bsums, int nb) {
    __shared__ int sh[256];
    int v = (threadIdx.x < nb) ? bsums[threadIdx.x] : 0;
    sh[threadIdx.x] = v;
    __syncthreads();
    for (int off = 1; off < 256; off <<= 1) {
        int t = (threadIdx.x >= off) ? sh[threadIdx.x - off] : 0;
        __syncthreads();
        sh[threadIdx.x] += t;
        __syncthreads();
    }
    if (threadIdx.x < nb) bsums[threadIdx.x] = sh[threadIdx.x] - v;  // exclusive
}

__global__ void scan3_kernel(int* rowoff, int* cursor, const int* __restrict__ bsums, int n) {
    int i = blockIdx.x * blockDim.x + threadIdx.x;
    if (i < n) {
        int r = rowoff[i] + bsums[i >> 10];
        rowoff[i] = r;
        cursor[i] = r;
    }
}

__global__ void scatter_kernel(const int* __restrict__ src, const int* __restrict__ dst,
                               const int* __restrict__ rid, int* cursor,
                               int* srcs, int* rids, int E) {
    int e = blockIdx.x * blockDim.x + threadIdx.x;
    if (e < E) {
        int p = atomicAdd(&cursor[dst[e]], 1);
        srcs[p] = src[e];
        rids[p] = rid[e];
    }
}

// ---------------- layernorm (warp per row) ----------------
__global__ void ln_kernel(const float* __restrict__ x, const float* __restrict__ g,
                          const float* __restrict__ b, float* __restrict__ y, int nrows) {
    int w = (blockIdx.x * blockDim.x + threadIdx.x) >> 5;
    if (w >= nrows) return;
    int lane = threadIdx.x & 31;
    float4 v = *(const float4*)(x + (long)w * D + lane * 4);
    float s = v.x + v.y + v.z + v.w;
    #pragma unroll
    for (int o = 16; o; o >>= 1) s += __shfl_xor_sync(0xffffffffu, s, o);
    float mean = s * (1.0f / 128.0f);
    float dx = v.x - mean, dy = v.y - mean, dz = v.z - mean, dw = v.w - mean;
    float q = dx * dx + dy * dy + dz * dz + dw * dw;
    #pragma unroll
    for (int o = 16; o; o >>= 1) q += __shfl_xor_sync(0xffffffffu, q, o);
    float inv = rsqrtf(q * (1.0f / 128.0f) + 1e-5f);
    float4 g4 = *(const float4*)(g + lane * 4);
    float4 b4 = *(const float4*)(b + lane * 4);
    float4 o4;
    o4.x = dx * inv * g4.x + b4.x;
    o4.y = dy * inv * g4.y + b4.y;
    o4.z = dz * inv * g4.z + b4.z;
    o4.w = dw * inv * g4.w + b4.w;
    *(float4*)(y + (long)w * D + lane * 4) = o4;
}

// ---------------- GEMM: Y[nrows,128] = X[nrows,128] @ W[128,128] ----------------
__global__ void __launch_bounds__(256) gemm128_kernel(const float* __restrict__ X,
                                                      const float* __restrict__ W,
                                                      float* __restrict__ Y, int nrows) {
    __shared__ float Xs[64 * 128];
    int r0 = blockIdx.x * 64;
    for (int idx = threadIdx.x; idx < 64 * 128; idx += 256) {
        int r = idx >> 7, c = idx & 127;
        int gr = r0 + r;
        Xs[idx] = (gr < nrows) ? X[(long)gr * D + c] : 0.0f;
    }
    __syncthreads();
    int tx = threadIdx.x & 31, ty = threadIdx.x >> 5;
    float4 acc[8];
    #pragma unroll
    for (int i = 0; i < 8; i++) acc[i] = make_float4(0.f, 0.f, 0.f, 0.f);
    const float4* W4 = (const float4*)W;
    for (int kk = 0; kk < 128; kk++) {
        float4 w = W4[kk * 32 + tx];
        #pragma unroll
        for (int ri = 0; ri < 8; ri++) {
            float xv = Xs[(ty * 8 + ri) * 128 + kk];
            acc[ri].x += xv * w.x;
            acc[ri].y += xv * w.y;
            acc[ri].z += xv * w.z;
            acc[ri].w += xv * w.w;
        }
    }
    #pragma unroll
    for (int ri = 0; ri < 8; ri++) {
        int gr = r0 + ty * 8 + ri;
        if (gr < nrows) ((float4*)Y)[(long)gr * 32 + tx] = acc[ri];
    }
}

// ---------------- attention + softmax (warp per dst node) ----------------
__global__ void attn_kernel(const int* __restrict__ rowoff, const int* __restrict__ deg,
                            const int* __restrict__ srcs, const int* __restrict__ rids,
                            const float* __restrict__ kb, const float* __restrict__ qb,
                            const float* __restrict__ relp, float* __restrict__ ex, int N) {
    int w = (blockIdx.x * blockDim.x + threadIdx.x) >> 5;
    if (w >= N) return;
    int lane = threadIdx.x & 31;
    int head = lane >> 2;
    int start = rowoff[w];
    int dg = deg[w];
    float4 q4 = *(const float4*)(qb + (long)w * D + lane * 4);
    float c = log1pf((float)dg) * 0.25f;  // log_in / sqrt(DH)
    float m = -INFINITY;
    for (int i = 0; i < dg; i++) {
        int p = start + i;
        int s = srcs[p];
        int r = rids[p];
        float4 k4 = *(const float4*)(kb + (long)s * D + lane * 4);
        float4 r4 = *(const float4*)(relp + (long)r * D + lane * 4);
        float part = k4.x * r4.x * q4.x + k4.y * r4.y * q4.y +
                     k4.z * r4.z * q4.z + k4.w * r4.w * q4.w;
        part += __shfl_xor_sync(0xffffffffu, part, 1);
        part += __shfl_xor_sync(0xffffffffu, part, 2);
        float logit = part * c;
        if ((lane & 3) == 0) ex[(long)p * H + head] = logit;
        m = fmaxf(m, logit);
    }
    // gather per-head max into lanes 0..7
    float mh = __shfl_sync(0xffffffffu, m, (lane & 7) * 4);
    if (lane < 8) {
        float sum = 0.0f;
        for (int i = 0; i < dg; i++) {
            long p = start + i;
            float l = ex[p * H + lane];
            float e = __expf(l - mh);
            sum += e;
            ex[p * H + lane] = e;
        }
        float scale = (sum > 0.0f) ? ((1.0f - ALPHA) / sum) : 0.0f;
        for (int i = 0; i < dg; i++) {
            long p = start + i;
            ex[p * H + lane] *= scale;
        }
    }
}

// ---------------- PPR diffusion hop (warp per dst node) ----------------
__global__ void hop_kernel(const int* __restrict__ rowoff, const int* __restrict__ deg,
                           const int* __restrict__ srcs, const float* __restrict__ ex,
                           const float* __restrict__ fin, const float* __restrict__ f0,
                           float* __restrict__ fout, int N) {
    int w = (blockIdx.x * blockDim.x + threadIdx.x) >> 5;
    if (w >= N) return;
    int lane = threadIdx.x & 31;
    int head = lane >> 2;
    int start = rowoff[w];
    int dg = deg[w];
    float4 acc = make_float4(0.f, 0.f, 0.f, 0.f);
    for (int i = 0; i < dg; i++) {
        int p = start + i;
        int s = srcs[p];
        float a = ex[(long)p * H + head];
        float4 f = *(const float4*)(fin + (long)s * D + lane * 4);
        acc.x += a * f.x;
        acc.y += a * f.y;
        acc.z += a * f.z;
        acc.w += a * f.w;
    }
    float4 z = *(const float4*)(f0 + (long)w * D + lane * 4);
    acc.x += ALPHA * z.x;
    acc.y += ALPHA * z.y;
    acc.z += ALPHA * z.z;
    acc.w += ALPHA * z.w;
    *(float4*)(fout + (long)w * D + lane * 4) = acc;
}

// ---------------- fused residual + LN + FFN + residual ----------------
// 64 rows per block, 512 threads, smem: ys[64*132] + hs[64*512]
#define FFN_SMEM ((64 * 132 + 64 * 512) * 4)
__global__ void __launch_bounds__(512) ffn_kernel(
    const float* __restrict__ feat, const float* __restrict__ ent,
    const float* __restrict__ gff, const float* __restrict__ bff,
    const float* __restrict__ W1, const float* __restrict__ b1,
    const float* __restrict__ W2, const float* __restrict__ b2,
    float* __restrict__ out, int nrows) {
    extern __shared__ float sm[];
    float* ys = sm;            // 64 x 132
    float* hs = sm + 64 * 132; // 64 x 512
    int r0 = blockIdx.x * 64;
    int tid = threadIdx.x;

    // LN phase: 16 warps x 4 rows, 8 lanes per row (16 elems each)
    {
        int warp = tid >> 5, lane = tid & 31;
        int lrow = warp * 4 + (lane >> 3);
        int seg = lane & 7;
        int grow = r0 + lrow;
        float vals[16];
        if (grow < nrows) {
            const float4* fp = (const float4*)(feat + (long)grow * D + seg * 16);
            const float4* ep = (const float4*)(ent + (long)grow * D + seg * 16);
            #pragma unroll
            for (int j = 0; j < 4; j++) {
                float4 a = fp[j], bb = ep[j];
                vals[j * 4 + 0] = a.x + bb.x;
                vals[j * 4 + 1] = a.y + bb.y;
                vals[j * 4 + 2] = a.z + bb.z;
                vals[j * 4 + 3] = a.w + bb.w;
            }
        } else {
            #pragma unroll
            for (int j = 0; j < 16; j++) vals[j] = 0.0f;
        }
        float s = 0.0f;
        #pragma unroll
        for (int j = 0; j < 16; j++) s += vals[j];
        s += __shfl_xor_sync(0xffffffffu, s, 1);
        s += __shfl_xor_sync(0xffffffffu, s, 2);
        s += __shfl_xor_sync(0xffffffffu, s, 4);
        float mean = s * (1.0f / 128.0f);
        float q = 0.0f;
        #pragma unroll
        for (int j = 0; j < 16; j++) {
            float d = vals[j] - mean;
            q += d * d;
        }
        q += __shfl_xor_sync(0xffffffffu, q, 1);
        q += __shfl_xor_sync(0xffffffffu, q, 2);
        q += __shfl_xor_sync(0xffffffffu, q, 4);
        float inv = rsqrtf(q * (1.0f / 128.0f) + 1e-5f);
        #pragma unroll
        for (int j = 0; j < 4; j++) {
            float4 g4 = ((const float4*)(gff + seg * 16))[j];
            float4 b4 = ((const float4*)(bff + seg * 16))[j];
            float4 o;
            o.x = (vals[j * 4 + 0] - mean) * inv * g4.x + b4.x;
            o.y = (vals[j * 4 + 1] - mean) * inv * g4.y + b4.y;
            o.z = (vals[j * 4 + 2] - mean) * inv * g4.z + b4.z;
            o.w = (vals[j * 4 + 3] - mean) * inv * g4.w + b4.w;
            *(float4*)(ys + lrow * 132 + seg * 16 + j * 4) = o;
        }
    }
    __syncthreads();

    // GEMM1: h = relu(y @ W1 + b1), tile 64x512
    {
        int ty = tid >> 6, tx = tid & 63;  // 8 row-groups x 8 rows, 8 cols each
        float acc[8][8];
        #pragma unroll
        for (int i = 0; i < 8; i++)
            #pragma unroll
            for (int j = 0; j < 8; j++) acc[i][j] = 0.0f;
        for (int kk = 0; kk < 128; kk++) {
            const float4* wp = (const float4*)(W1 + (long)kk * 512 + tx * 8);
            float4 wa = wp[0], wb = wp[1];
            #pragma unroll
            for (int ri = 0; ri < 8; ri++) {
                float yv = ys[(ty * 8 + ri) * 132 + kk];
                acc[ri][0] += yv * wa.x;
                acc[ri][1] += yv * wa.y;
                acc[ri][2] += yv * wa.z;
                acc[ri][3] += yv * wa.w;
                acc[ri][4] += yv * wb.x;
                acc[ri][5] += yv * wb.y;
                acc[ri][6] += yv * wb.z;
                acc[ri][7] += yv * wb.w;
            }
        }
        float4 ba = ((const float4*)(b1 + tx * 8))[0];
        float4 bb = ((const float4*)(b1 + tx * 8))[1];
        float bv[8] = {ba.x, ba.y, ba.z, ba.w, bb.x, bb.y, bb.z, bb.w};
        #pragma unroll
        for (int ri = 0; ri < 8; ri++) {
            #pragma unroll
            for (int jj = 0; jj < 8; jj++) {
                hs[(ty * 8 + ri) * 512 + tx * 8 + jj] = fmaxf(acc[ri][jj] + bv[jj], 0.0f);
            }
        }
    }
    __syncthreads();

    // GEMM2: out = h @ W2 + b2 + rst
    {
        int ty2 = tid >> 5, tx2 = tid & 31;  // 16 row-groups x 4 rows, 4 cols (float4)
        float4 acc2[4];
        #pragma unroll
        for (int i = 0; i < 4; i++) acc2[i] = make_float4(0.f, 0.f, 0.f, 0.f);
        for (int kk = 0; kk < 512; kk++) {
            float4 w = ((const float4*)(W2 + (long)kk * 128))[tx2];
            #pragma unroll
            for (int ri = 0; ri < 4; ri++) {
                float hv = hs[(ty2 * 4 + ri) * 512 + kk];
                acc2[ri].x += hv * w.x;
                acc2[ri].y += hv * w.y;
                acc2[ri].z += hv * w.z;
                acc2[ri].w += hv * w.w;
            }
        }
        float4 b2v = ((const float4*)b2)[tx2];
        #pragma unroll
        for (int ri = 0; ri < 4; ri++) {
            int grow = r0 + ty2 * 4 + ri;
            if (grow < nrows) {
                float4 f = ((const float4*)(feat + (long)grow * D))[tx2];
                float4 e = ((const float4*)(ent + (long)grow * D))[tx2];
                float4 o;
                o.x = acc2[ri].x + b2v.x + f.x + e.x;
                o.y = acc2[ri].y + b2v.y + f.y + e.y;
                o.z = acc2[ri].z + b2v.z + f.z + e.z;
                o.w = acc2[ri].w + b2v.w + f.w + e.w;
                ((float4*)(out + (long)grow * D))[tx2] = o;
            }
        }
    }
}

// ---------------- launch ----------------
extern "C" void kernel_launch(void* const* d_in, const int* in_sizes, int n_in,
                              void* d_out, int out_size) {
    const float* ent    = (const float*)d_in[0];
    const float* relf   = (const float*)d_in[1];
    const float* W_head = (const float*)d_in[2];
    const float* W_tail = (const float*)d_in[3];
    const float* W_ent  = (const float*)d_in[4];
    const float* W_rel  = (const float*)d_in[5];
    const float* g_ent  = (const float*)d_in[6];
    const float* b_ent  = (const float*)d_in[7];
    const float* g_rel  = (const float*)d_in[8];
    const float* b_rel  = (const float*)d_in[9];
    const float* g_ff   = (const float*)d_in[10];
    const float* b_ff   = (const float*)d_in[11];
    const float* W1     = (const float*)d_in[12];
    const float* b1     = (const float*)d_in[13];
    const float* W2     = (const float*)d_in[14];
    const float* b2     = (const float*)d_in[15];
    const int*   src    = (const int*)d_in[16];
    const int*   dst    = (const int*)d_in[17];
    const int*   rid    = (const int*)d_in[18];
    float* out = (float*)d_out;

    int N = in_sizes[0] / D;
    int R = in_sizes[1] / D;
    int E = in_sizes[16];

    float *p_xn, *p_k, *p_q, *p_v, *p_fA, *p_fB, *p_ex, *p_relx, *p_relp;
    int *p_deg, *p_rowoff, *p_cursor, *p_srcs, *p_rids, *p_bsums;
    cudaGetSymbolAddress((void**)&p_xn, d_xn);
    cudaGetSymbolAddress((void**)&p_k, d_k);
    cudaGetSymbolAddress((void**)&p_q, d_q);
    cudaGetSymbolAddress((void**)&p_v, d_v);
    cudaGetSymbolAddress((void**)&p_fA, d_featA);
    cudaGetSymbolAddress((void**)&p_fB, d_featB);
    cudaGetSymbolAddress((void**)&p_ex, d_ex);
    cudaGetSymbolAddress((void**)&p_relx, d_relx);
    cudaGetSymbolAddress((void**)&p_relp, d_relp);
    cudaGetSymbolAddress((void**)&p_deg, d_deg);
    cudaGetSymbolAddress((void**)&p_rowoff, d_rowoff);
    cudaGetSymbolAddress((void**)&p_cursor, d_cursor);
    cudaGetSymbolAddress((void**)&p_srcs, d_srcs);
    cudaGetSymbolAddress((void**)&p_rids, d_rids);
    cudaGetSymbolAddress((void**)&p_bsums, d_bsums);

    cudaFuncSetAttribute(ffn_kernel, cudaFuncAttributeMaxDynamicSharedMemorySize, FFN_SMEM);

    int nb = (N + 1023) / 1024;

    // CSR build
    zero_deg_kernel<<<(N + 255) / 256, 256>>>(p_deg, N);
    hist_kernel<<<(E + 255) / 256, 256>>>(dst, p_deg, E);
    scan1_kernel<<<nb, 1024>>>(p_deg, p_rowoff, p_bsums, N);
    scan2_kernel<<<1, 256>>>(p_bsums, nb);
    scan3_kernel<<<(N + 255) / 256, 256>>>(p_rowoff, p_cursor, p_bsums, N);
    scatter_kernel<<<(E + 255) / 256, 256>>>(src, dst, rid, p_cursor, p_srcs, p_rids, E);

    // node/rel projections
    ln_kernel<<<(N + 7) / 8, 256>>>(ent, g_ent, b_ent, p_xn, N);
    ln_kernel<<<(R + 7) / 8, 256>>>(relf, g_rel, b_rel, p_relx, R);
    gemm128_kernel<<<(N + 63) / 64, 256>>>(p_xn, W_head, p_k, N);
    gemm128_kernel<<<(N + 63) / 64, 256>>>(p_xn, W_tail, p_q, N);
    gemm128_kernel<<<(N + 63) / 64, 256>>>(p_xn, W_ent, p_v, N);
    gemm128_kernel<<<(R + 63) / 64, 256>>>(p_relx, W_rel, p_relp, R);

    // attention + softmax (weights folded with (1-alpha)/denom)
    attn_kernel<<<(N + 7) / 8, 256>>>(p_rowoff, p_deg, p_srcs, p_rids,
                                      p_k, p_q, p_relp, p_ex, N);

    // 4 PPR hops: v -> A -> B -> A -> B
    hop_kernel<<<(N + 7) / 8, 256>>>(p_rowoff, p_deg, p_srcs, p_ex, p_v,  p_v, p_fA, N);
    hop_kernel<<<(N + 7) / 8, 256>>>(p_rowoff, p_deg, p_srcs, p_ex, p_fA, p_v, p_fB, N);
    hop_kernel<<<(N + 7) / 8, 256>>>(p_rowoff, p_deg, p_srcs, p_ex, p_fB, p_v, p_fA, N);
    hop_kernel<<<(N + 7) / 8, 256>>>(p_rowoff, p_deg, p_srcs, p_ex, p_fA, p_v, p_fB, N);

    // residual + LN + FFN + residual
    ffn_kernel<<<(N + 63) / 64, 512, FFN_SMEM>>>(p_fB, ent, g_ff, b_ff,
                                                 W1, b1, W2, b2, out, N);
}

// round 2
// speedup vs baseline: 1.6734x; 1.6734x over previous
#include <cuda_runtime.h>
#include <cuda_bf16.h>
#include <math.h>
#include <stdint.h>

#define D 128
#define H 8
#define DH 16
#define NMAX 100000
#define EMAX 1600000
#define RMAX 128
#define ALPHA 0.1f

// ---------------- scratch (device globals; no allocations) ----------------
__device__ float d_xn[NMAX * D];
__device__ float d_k[NMAX * D];
__device__ float d_q[NMAX * D];
__device__ float d_v[NMAX * D];
__device__ float d_featA[NMAX * D];
__device__ float d_featB[NMAX * D];
__device__ float d_ex[EMAX * H];
__device__ float d_relx[RMAX * D];
__device__ float d_relp[RMAX * D];
__device__ float d_h[NMAX * 512];
__device__ int   d_deg[NMAX];
__device__ int   d_rowoff[NMAX];
__device__ int   d_cursor[NMAX];
__device__ int   d_srcs[EMAX];
__device__ int   d_rids[EMAX];
__device__ int   d_bsums[256];

// ---------------- CSR build ----------------
__global__ void zero_deg_kernel(int* deg, int n) {
    int i = blockIdx.x * blockDim.x + threadIdx.x;
    if (i < n) deg[i] = 0;
}

__global__ void hist_kernel(const int* __restrict__ dst, int* deg, int E) {
    int e = blockIdx.x * blockDim.x + threadIdx.x;
    if (e < E) atomicAdd(&deg[dst[e]], 1);
}

__global__ void scan1_kernel(const int* __restrict__ deg, int* rowoff, int* bsums, int n) {
    __shared__ int sh[1024];
    int i = blockIdx.x * 1024 + threadIdx.x;
    int v = (i < n) ? deg[i] : 0;
    sh[threadIdx.x] = v;
    __syncthreads();
    for (int off = 1; off < 1024; off <<= 1) {
        int t = (threadIdx.x >= off) ? sh[threadIdx.x - off] : 0;
        __syncthreads();
        sh[threadIdx.x] += t;
        __syncthreads();
    }
    if (i < n) rowoff[i] = sh[threadIdx.x] - v;  // exclusive
    if (threadIdx.x == 1023) bsums[blockIdx.x] = sh[1023];
}

__global__ void scan2_kernel(int* bsums, int nb) {
    __shared__ int sh[256];
    int v = (threadIdx.x < nb) ? bsums[threadIdx.x] : 0;
    sh[threadIdx.x] = v;
    __syncthreads();
    for (int off = 1; off < 256; off <<= 1) {
        int t = (threadIdx.x >= off) ? sh[threadIdx.x - off] : 0;
        __syncthreads();
        sh[threadIdx.x] += t;
        __syncthreads();
    }
    if (threadIdx.x < nb) bsums[threadIdx.x] = sh[threadIdx.x] - v;  // exclusive
}

__global__ void scan3_kernel(int* rowoff, int* cursor, const int* __restrict__ bsums, int n) {
    int i = blockIdx.x * blockDim.x + threadIdx.x;
    if (i < n) {
        int r = rowoff[i] + bsums[i >> 10];
        rowoff[i] = r;
        cursor[i] = r;
    }
}

__global__ void scatter_kernel(const int* __restrict__ src, const int* __restrict__ dst,
                               const int* __restrict__ rid, int* cursor,
                               int* srcs, int* rids, int E) {
    int e = blockIdx.x * blockDim.x + threadIdx.x;
    if (e < E) {
        int p = atomicAdd(&cursor[dst[e]], 1);
        srcs[p] = src[e];
        rids[p] = rid[e];
    }
}

// ---------------- layernorm (warp per row) ----------------
__global__ void ln_kernel(const float* __restrict__ x, const float* __restrict__ g,
                          const float* __restrict__ b, float* __restrict__ y, int nrows) {
    int w = (blockIdx.x * blockDim.x + threadIdx.x) >> 5;
    if (w >= nrows) return;
    int lane = threadIdx.x & 31;
    float4 v = *(const float4*)(x + (long)w * D + lane * 4);
    float s = v.x + v.y + v.z + v.w;
    #pragma unroll
    for (int o = 16; o; o >>= 1) s += __shfl_xor_sync(0xffffffffu, s, o);
    float mean = s * (1.0f / 128.0f);
    float dx = v.x - mean, dy = v.y - mean, dz = v.z - mean, dw = v.w - mean;
    float q = dx * dx + dy * dy + dz * dz + dw * dw;
    #pragma unroll
    for (int o = 16; o; o >>= 1) q += __shfl_xor_sync(0xffffffffu, q, o);
    float inv = rsqrtf(q * (1.0f / 128.0f) + 1e-5f);
    float4 g4 = *(const float4*)(g + lane * 4);
    float4 b4 = *(const float4*)(b + lane * 4);
    float4 o4;
    o4.x = dx * inv * g4.x + b4.x;
    o4.y = dy * inv * g4.y + b4.y;
    o4.z = dz * inv * g4.z + b4.z;
    o4.w = dw * inv * g4.w + b4.w;
    *(float4*)(y + (long)w * D + lane * 4) = o4;
}

// residual + layernorm: y = LN(feat+ent)*g+b, rst = feat+ent
__global__ void resid_ln_kernel(const float* __restrict__ feat, const float* __restrict__ ent,
                                const float* __restrict__ g, const float* __restrict__ b,
                                float* __restrict__ y, float* __restrict__ rst, int nrows) {
    int w = (blockIdx.x * blockDim.x + threadIdx.x) >> 5;
    if (w >= nrows) return;
    int lane = threadIdx.x & 31;
    float4 f = *(const float4*)(feat + (long)w * D + lane * 4);
    float4 e = *(const float4*)(ent + (long)w * D + lane * 4);
    float4 v;
    v.x = f.x + e.x; v.y = f.y + e.y; v.z = f.z + e.z; v.w = f.w + e.w;
    *(float4*)(rst + (long)w * D + lane * 4) = v;
    float s = v.x + v.y + v.z + v.w;
    #pragma unroll
    for (int o = 16; o; o >>= 1) s += __shfl_xor_sync(0xffffffffu, s, o);
    float mean = s * (1.0f / 128.0f);
    float dx = v.x - mean, dy = v.y - mean, dz = v.z - mean, dw = v.w - mean;
    float q = dx * dx + dy * dy + dz * dz + dw * dw;
    #pragma unroll
    for (int o = 16; o; o >>= 1) q += __shfl_xor_sync(0xffffffffu, q, o);
    float inv = rsqrtf(q * (1.0f / 128.0f) + 1e-5f);
    float4 g4 = *(const float4*)(g + lane * 4);
    float4 b4 = *(const float4*)(b + lane * 4);
    float4 o4;
    o4.x = dx * inv * g4.x + b4.x;
    o4.y = dy * inv * g4.y + b4.y;
    o4.z = dz * inv * g4.z + b4.z;
    o4.w = dw * inv * g4.w + b4.w;
    *(float4*)(y + (long)w * D + lane * 4) = o4;
}

// ---------------- tf32 tensor-core GEMM ----------------
__device__ __forceinline__ uint32_t f2tf32(float x) {
    uint32_t r;
    asm("cvt.rna.tf32.f32 %0, %1;" : "=r"(r) : "f"(x));
    return r;
}

__device__ __forceinline__ void mma_tf32(float* c, const uint32_t* a, const uint32_t* b) {
    asm volatile(
        "mma.sync.aligned.m16n8k8.row.col.f32.tf32.tf32.f32 "
        "{%0,%1,%2,%3}, {%4,%5,%6,%7}, {%8,%9}, {%0,%1,%2,%3};\n"
        : "+f"(c[0]), "+f"(c[1]), "+f"(c[2]), "+f"(c[3])
        : "r"(a[0]), "r"(a[1]), "r"(a[2]), "r"(a[3]), "r"(b[0]), "r"(b[1]));
}

// C[M,Nc] = X[M,K] @ W[K,Nc] (+epilogue). Block tile 128x128, BK=32, 256 thr.
// EPI: 0 = none; 1 = relu(acc+bias); 2 = acc + bias + rst
#define MM_SMEM ((2 * 128 * 36 + 2 * 32 * 132) * 4)
template<int EPI>
__global__ void __launch_bounds__(256) mm_tf32_kernel(
    const float* __restrict__ X, const float* __restrict__ W,
    const float* __restrict__ bias, const float* __restrict__ rst,
    float* __restrict__ Y, int M, int K, int Nc)
{
    extern __shared__ uint32_t smem_u[];
    uint32_t* Abase = smem_u;               // 2 bufs of [128][36]
    uint32_t* Bbase = smem_u + 2 * 128 * 36; // 2 bufs of [32][132]
    const int tid = threadIdx.x;
    const int lane = tid & 31;
    const int warp = tid >> 5;
    const int m_off = (warp & 3) * 32;
    const int n_off = (warp >> 2) * 64;
    const int r0 = blockIdx.x * 128;
    const int n0 = blockIdx.y * 128;

    float acc[2][8][4];
    #pragma unroll
    for (int mi = 0; mi < 2; mi++)
        #pragma unroll
        for (int ni = 0; ni < 8; ni++)
            #pragma unroll
            for (int j = 0; j < 4; j++) acc[mi][ni][j] = 0.0f;

    const int T = K >> 5;
    float4 ra[4], rb[4];

    // prologue: load tile 0
    #pragma unroll
    for (int i = 0; i < 4; i++) {
        int pos = tid + i * 256;
        int row = pos >> 3, c4 = pos & 7;
        int gr = r0 + row;
        ra[i] = (gr < M) ? *(const float4*)(X + (long)gr * K + c4 * 4)
                         : make_float4(0.f, 0.f, 0.f, 0.f);
        int brow = pos >> 5, bc4 = pos & 31;
        rb[i] = *(const float4*)(W + (long)brow * Nc + n0 + bc4 * 4);
    }
    {
        uint32_t* As = Abase;
        uint32_t* Bs = Bbase;
        #pragma unroll
        for (int i = 0; i < 4; i++) {
            int pos = tid + i * 256;
            int row = pos >> 3, c4 = pos & 7;
            As[row * 36 + c4 * 4 + 0] = f2tf32(ra[i].x);
            As[row * 36 + c4 * 4 + 1] = f2tf32(ra[i].y);
            As[row * 36 + c4 * 4 + 2] = f2tf32(ra[i].z);
            As[row * 36 + c4 * 4 + 3] = f2tf32(ra[i].w);
            int brow = pos >> 5, bc4 = pos & 31;
            Bs[brow * 132 + bc4 * 4 + 0] = f2tf32(rb[i].x);
            Bs[brow * 132 + bc4 * 4 + 1] = f2tf32(rb[i].y);
            Bs[brow * 132 + bc4 * 4 + 2] = f2tf32(rb[i].z);
            Bs[brow * 132 + bc4 * 4 + 3] = f2tf32(rb[i].w);
        }
    }
    __syncthreads();

    for (int t = 0; t < T; t++) {
        if (t + 1 < T) {
            #pragma unroll
            for (int i = 0; i < 4; i++) {
                int pos = tid + i * 256;
                int row = pos >> 3, c4 = pos & 7;
                int gr = r0 + row;
                int gk = (t + 1) * 32 + c4 * 4;
                ra[i] = (gr < M) ? *(const float4*)(X + (long)gr * K + gk)
                                 : make_float4(0.f, 0.f, 0.f, 0.f);
                int brow = pos >> 5, bc4 = pos & 31;
                rb[i] = *(const float4*)(W + (long)((t + 1) * 32 + brow) * Nc + n0 + bc4 * 4);
            }
        }
        uint32_t* As = Abase + (t & 1) * 128 * 36;
        uint32_t* Bs = Bbase + (t & 1) * 32 * 132;
        #pragma unroll
        for (int ks = 0; ks < 4; ks++) {
            int kk = ks * 8 + (lane & 3);
            uint32_t a[2][4];
            #pragma unroll
            for (int mi = 0; mi < 2; mi++) {
                int r = m_off + mi * 16 + (lane >> 2);
                a[mi][0] = As[r * 36 + kk];
                a[mi][1] = As[(r + 8) * 36 + kk];
                a[mi][2] = As[r * 36 + kk + 4];
                a[mi][3] = As[(r + 8) * 36 + kk + 4];
            }
            uint32_t b[8][2];
            #pragma unroll
            for (int ni = 0; ni < 8; ni++) {
                int cc = n_off + ni * 8 + (lane >> 2);
                b[ni][0] = Bs[kk * 132 + cc];
                b[ni][1] = Bs[(kk + 4) * 132 + cc];
            }
            #pragma unroll
            for (int mi = 0; mi < 2; mi++)
                #pragma unroll
                for (int ni = 0; ni < 8; ni++)
                    mma_tf32(acc[mi][ni], a[mi], b[ni]);
        }
        if (t + 1 < T) {
            __syncthreads();
            uint32_t* As2 = Abase + ((t + 1) & 1) * 128 * 36;
            uint32_t* Bs2 = Bbase + ((t + 1) & 1) * 32 * 132;
            #pragma unroll
            for (int i = 0; i < 4; i++) {
                int pos = tid + i * 256;
                int row = pos >> 3, c4 = pos & 7;
                As2[row * 36 + c4 * 4 + 0] = f2tf32(ra[i].x);
                As2[row * 36 + c4 * 4 + 1] = f2tf32(ra[i].y);
                As2[row * 36 + c4 * 4 + 2] = f2tf32(ra[i].z);
                As2[row * 36 + c4 * 4 + 3] = f2tf32(ra[i].w);
                int brow = pos >> 5, bc4 = pos & 31;
                Bs2[brow * 132 + bc4 * 4 + 0] = f2tf32(rb[i].x);
                Bs2[brow * 132 + bc4 * 4 + 1] = f2tf32(rb[i].y);
                Bs2[brow * 132 + bc4 * 4 + 2] = f2tf32(rb[i].z);
                Bs2[brow * 132 + bc4 * 4 + 3] = f2tf32(rb[i].w);
            }
            __syncthreads();
        }
    }

    // epilogue
    #pragma unroll
    for (int mi = 0; mi < 2; mi++) {
        #pragma unroll
        for (int half = 0; half < 2; half++) {
            int row = m_off + mi * 16 + (lane >> 2) + half * 8;
            int gr = r0 + row;
            if (gr >= M) continue;
            #pragma unroll
            for (int ni = 0; ni < 8; ni++) {
                int col = n_off + ni * 8 + (lane & 3) * 2;
                float v0 = acc[mi][ni][half * 2 + 0];
                float v1 = acc[mi][ni][half * 2 + 1];
                if (EPI == 1) {
                    v0 = fmaxf(v0 + bias[n0 + col], 0.0f);
                    v1 = fmaxf(v1 + bias[n0 + col + 1], 0.0f);
                } else if (EPI == 2) {
                    v0 += bias[n0 + col] + rst[(long)gr * Nc + n0 + col];
                    v1 += bias[n0 + col + 1] + rst[(long)gr * Nc + n0 + col + 1];
                }
                *(float2*)(Y + (long)gr * Nc + n0 + col) = make_float2(v0, v1);
            }
        }
    }
}

// ---------------- attention + softmax (warp per dst node, no max pass) ----------------
__global__ void attn_kernel(const int* __restrict__ rowoff, const int* __restrict__ deg,
                            const int* __restrict__ srcs, const int* __restrict__ rids,
                            const float* __restrict__ kb, const float* __restrict__ qb,
                            const float* __restrict__ relp, float* __restrict__ ex, int N) {
    int w = (blockIdx.x * blockDim.x + threadIdx.x) >> 5;
    if (w >= N) return;
    int lane = threadIdx.x & 31;
    int head4 = lane >> 2;
    int start = rowoff[w];
    int dg = deg[w];
    float4 q4 = *(const float4*)(qb + (long)w * D + lane * 4);
    float c = log1pf((float)dg) * 0.25f;  // log_in / sqrt(DH)
    float sum = 0.0f;
    for (int i = 0; i < dg; i++) {
        int p = start + i;
        int s = srcs[p];
        int r = rids[p];
        float4 k4 = *(const float4*)(kb + (long)s * D + lane * 4);
        float4 r4 = *(const float4*)(relp + (long)r * D + lane * 4);
        float part = k4.x * r4.x * q4.x + k4.y * r4.y * q4.y +
                     k4.z * r4.z * q4.z + k4.w * r4.w * q4.w;
        part += __shfl_xor_sync(0xffffffffu, part, 1);
        part += __shfl_xor_sync(0xffffffffu, part, 2);
        // logits are tiny (|.|<~10): exp without max-subtraction is safe and
        // the softmax ratio is identical.
        float e = __expf(part * c);
        if ((lane & 3) == 0) ex[(long)p * H + head4] = e;
        sum += e;
    }
    // sum for head (lane&7) lives in quad (lane&7)
    float s_h = __shfl_sync(0xffffffffu, sum, (lane & 7) * 4);
    float scale = (s_h > 0.0f) ? ((1.0f - ALPHA) / s_h) : 0.0f;
    int sub = lane >> 3, head = lane & 7;
    for (int i = sub; i < dg; i += 4) {
        long p = start + i;
        ex[p * H + head] *= scale;
    }
}

// ---------------- PPR diffusion hop (warp per dst node) ----------------
__global__ void hop_kernel(const int* __restrict__ rowoff, const int* __restrict__ deg,
                           const int* __restrict__ srcs, const float* __restrict__ ex,
                           const float* __restrict__ fin, const float* __restrict__ f0,
                           float* __restrict__ fout, int N) {
    int w = (blockIdx.x * blockDim.x + threadIdx.x) >> 5;
    if (w >= N) return;
    int lane = threadIdx.x & 31;
    int head = lane >> 2;
    int start = rowoff[w];
    int dg = deg[w];
    float4 acc = make_float4(0.f, 0.f, 0.f, 0.f);
    for (int i = 0; i < dg; i++) {
        int p = start + i;
        int s = srcs[p];
        float a = ex[(long)p * H + head];
        float4 f = *(const float4*)(fin + (long)s * D + lane * 4);
        acc.x += a * f.x;
        acc.y += a * f.y;
        acc.z += a * f.z;
        acc.w += a * f.w;
    }
    float4 z = *(const float4*)(f0 + (long)w * D + lane * 4);
    acc.x += ALPHA * z.x;
    acc.y += ALPHA * z.y;
    acc.z += ALPHA * z.z;
    acc.w += ALPHA * z.w;
    *(float4*)(fout + (long)w * D + lane * 4) = acc;
}

// ---------------- launch ----------------
extern "C" void kernel_launch(void* const* d_in, const int* in_sizes, int n_in,
                              void* d_out, int out_size) {
    const float* ent    = (const float*)d_in[0];
    const float* relf   = (const float*)d_in[1];
    const float* W_head = (const float*)d_in[2];
    const float* W_tail = (const float*)d_in[3];
    const float* W_ent  = (const float*)d_in[4];
    const float* W_rel  = (const float*)d_in[5];
    const float* g_ent  = (const float*)d_in[6];
    const float* b_ent  = (const float*)d_in[7];
    const float* g_rel  = (const float*)d_in[8];
    const float* b_rel  = (const float*)d_in[9];
    const float* g_ff   = (const float*)d_in[10];
    const float* b_ff   = (const float*)d_in[11];
    const float* W1     = (const float*)d_in[12];
    const float* b1     = (const float*)d_in[13];
    const float* W2     = (const float*)d_in[14];
    const float* b2     = (const float*)d_in[15];
    const int*   src    = (const int*)d_in[16];
    const int*   dst    = (const int*)d_in[17];
    const int*   rid    = (const int*)d_in[18];
    float* out = (float*)d_out;

    int N = in_sizes[0] / D;
    int R = in_sizes[1] / D;
    int E = in_sizes[16];

    float *p_xn, *p_k, *p_q, *p_v, *p_fA, *p_fB, *p_ex, *p_relx, *p_relp, *p_h;
    int *p_deg, *p_rowoff, *p_cursor, *p_srcs, *p_rids, *p_bsums;
    cudaGetSymbolAddress((void**)&p_xn, d_xn);
    cudaGetSymbolAddress((void**)&p_k, d_k);
    cudaGetSymbolAddress((void**)&p_q, d_q);
    cudaGetSymbolAddress((void**)&p_v, d_v);
    cudaGetSymbolAddress((void**)&p_fA, d_featA);
    cudaGetSymbolAddress((void**)&p_fB, d_featB);
    cudaGetSymbolAddress((void**)&p_ex, d_ex);
    cudaGetSymbolAddress((void**)&p_relx, d_relx);
    cudaGetSymbolAddress((void**)&p_relp, d_relp);
    cudaGetSymbolAddress((void**)&p_h, d_h);
    cudaGetSymbolAddress((void**)&p_deg, d_deg);
    cudaGetSymbolAddress((void**)&p_rowoff, d_rowoff);
    cudaGetSymbolAddress((void**)&p_cursor, d_cursor);
    cudaGetSymbolAddress((void**)&p_srcs, d_srcs);
    cudaGetSymbolAddress((void**)&p_rids, d_rids);
    cudaGetSymbolAddress((void**)&p_bsums, d_bsums);

    cudaFuncSetAttribute(mm_tf32_kernel<0>, cudaFuncAttributeMaxDynamicSharedMemorySize, MM_SMEM);
    cudaFuncSetAttribute(mm_tf32_kernel<1>, cudaFuncAttributeMaxDynamicSharedMemorySize, MM_SMEM);
    cudaFuncSetAttribute(mm_tf32_kernel<2>, cudaFuncAttributeMaxDynamicSharedMemorySize, MM_SMEM);

    int nb = (N + 1023) / 1024;
    int mblocks = (N + 127) / 128;

    // CSR build
    zero_deg_kernel<<<(N + 255) / 256, 256>>>(p_deg, N);
    hist_kernel<<<(E + 255) / 256, 256>>>(dst, p_deg, E);
    scan1_kernel<<<nb, 1024>>>(p_deg, p_rowoff, p_bsums, N);
    scan2_kernel<<<1, 256>>>(p_bsums, nb);
    scan3_kernel<<<(N + 255) / 256, 256>>>(p_rowoff, p_cursor, p_bsums, N);
    scatter_kernel<<<(E + 255) / 256, 256>>>(src, dst, rid, p_cursor, p_srcs, p_rids, E);

    // node/rel projections (tf32 tensor cores)
    ln_kernel<<<(N + 7) / 8, 256>>>(ent, g_ent, b_ent, p_xn, N);
    ln_kernel<<<(R + 7) / 8, 256>>>(relf, g_rel, b_rel, p_relx, R);
    mm_tf32_kernel<0><<<dim3(mblocks, 1), 256, MM_SMEM>>>(p_xn, W_head, nullptr, nullptr, p_k, N, 128, 128);
    mm_tf32_kernel<0><<<dim3(mblocks, 1), 256, MM_SMEM>>>(p_xn, W_tail, nullptr, nullptr, p_q, N, 128, 128);
    mm_tf32_kernel<0><<<dim3(mblocks, 1), 256, MM_SMEM>>>(p_xn, W_ent,  nullptr, nullptr, p_v, N, 128, 128);
    mm_tf32_kernel<0><<<dim3(1, 1), 256, MM_SMEM>>>(p_relx, W_rel, nullptr, nullptr, p_relp, R, 128, 128);

    // attention + softmax (weights folded with (1-alpha)/denom)
    attn_kernel<<<(N + 7) / 8, 256>>>(p_rowoff, p_deg, p_srcs, p_rids,
                                      p_k, p_q, p_relp, p_ex, N);

    // 4 PPR hops: v -> A -> B -> A -> B
    hop_kernel<<<(N + 7) / 8, 256>>>(p_rowoff, p_deg, p_srcs, p_ex, p_v,  p_v, p_fA, N);
    hop_kernel<<<(N + 7) / 8, 256>>>(p_rowoff, p_deg, p_srcs, p_ex, p_fA, p_v, p_fB, N);
    hop_kernel<<<(N + 7) / 8, 256>>>(p_rowoff, p_deg, p_srcs, p_ex, p_fB, p_v, p_fA, N);
    hop_kernel<<<(N + 7) / 8, 256>>>(p_rowoff, p_deg, p_srcs, p_ex, p_fA, p_v, p_fB, N);

    // residual + LN (y into d_xn, rst into d_q — both free now)
    resid_ln_kernel<<<(N + 7) / 8, 256>>>(p_fB, ent, g_ff, b_ff, p_xn, p_q, N);

    // FFN: h = relu(y@W1+b1); out = h@W2 + b2 + rst
    mm_tf32_kernel<1><<<dim3(mblocks, 4), 256, MM_SMEM>>>(p_xn, W1, b1, nullptr, p_h, N, 128, 512);
    mm_tf32_kernel<2><<<dim3(mblocks, 1), 256, MM_SMEM>>>(p_h, W2, b2, p_q, out, N, 512, 128);
}

// round 3
// speedup vs baseline: 1.9243x; 1.1500x over previous
#include <cuda_runtime.h>
#include <cuda_fp16.h>
#include <math.h>
#include <stdint.h>

#define D 128
#define H 8
#define NMAX 100000
#define EMAX 1600000
#define RMAX 128
#define ALPHA 0.1f

// ---------------- scratch (device globals; no allocations) ----------------
__device__ float  d_xn[NMAX * D];     // LN(ent); later y = LN(rst)
__device__ float  d_q[NMAX * D];      // q projection; later rst = feat + ent
__device__ __half d_kh[NMAX * D];
__device__ __half d_vh[NMAX * D];
__device__ __half d_fA[NMAX * D];
__device__ __half d_fB[NMAX * D];
__device__ __half d_hh[NMAX * 512];
__device__ float  d_ex[EMAX * H];
__device__ float  d_nscale[NMAX * H];
__device__ float  d_relx[RMAX * D];
__device__ float  d_relp[RMAX * D];
__device__ int    d_deg[NMAX];
__device__ int    d_rowoff[NMAX];
__device__ int    d_cursor[NMAX];
__device__ int    d_srcs[EMAX];
__device__ int    d_rids[EMAX];
__device__ int    d_bsums[256];

// ---------------- typed load/store helpers ----------------
__device__ __forceinline__ float4 ld4(const float* p) { return *(const float4*)p; }
__device__ __forceinline__ float4 ld4(const __half* p) {
    float2 r = *(const float2*)p;
    __half2 h0 = ((const __half2*)&r)[0];
    __half2 h1 = ((const __half2*)&r)[1];
    float2 a = __half22float2(h0), b = __half22float2(h1);
    return make_float4(a.x, a.y, b.x, b.y);
}
__device__ __forceinline__ void st2(float* p, float a, float b) {
    *(float2*)p = make_float2(a, b);
}
__device__ __forceinline__ void st2(__half* p, float a, float b) {
    *(__half2*)p = __floats2half2_rn(a, b);
}

// ---------------- CSR build ----------------
__global__ void zero_deg_kernel(int* deg, int n) {
    int i = blockIdx.x * blockDim.x + threadIdx.x;
    if (i < n) deg[i] = 0;
}

__global__ void hist_kernel(const int* __restrict__ dst, int* deg, int E) {
    int e = blockIdx.x * blockDim.x + threadIdx.x;
    if (e < E) atomicAdd(&deg[dst[e]], 1);
}

__global__ void scan1_kernel(const int* __restrict__ deg, int* rowoff, int* bsums, int n) {
    __shared__ int sh[1024];
    int i = blockIdx.x * 1024 + threadIdx.x;
    int v = (i < n) ? deg[i] : 0;
    sh[threadIdx.x] = v;
    __syncthreads();
    for (int off = 1; off < 1024; off <<= 1) {
        int t = (threadIdx.x >= off) ? sh[threadIdx.x - off] : 0;
        __syncthreads();
        sh[threadIdx.x] += t;
        __syncthreads();
    }
    if (i < n) rowoff[i] = sh[threadIdx.x] - v;  // exclusive
    if (threadIdx.x == 1023) bsums[blockIdx.x] = sh[1023];
}

__global__ void scan2_kernel(int* bsums, int nb) {
    __shared__ int sh[256];
    int v = (threadIdx.x < nb) ? bsums[threadIdx.x] : 0;
    sh[threadIdx.x] = v;
    __syncthreads();
    for (int off = 1; off < 256; off <<= 1) {
        int t = (threadIdx.x >= off) ? sh[threadIdx.x - off] : 0;
        __syncthreads();
        sh[threadIdx.x] += t;
        __syncthreads();
    }
    if (threadIdx.x < nb) bsums[threadIdx.x] = sh[threadIdx.x] - v;  // exclusive
}

__global__ void scan3_kernel(int* rowoff, int* cursor, const int* __restrict__ bsums, int n) {
    int i = blockIdx.x * blockDim.x + threadIdx.x;
    if (i < n) {
        int r = rowoff[i] + bsums[i >> 10];
        rowoff[i] = r;
        cursor[i] = r;
    }
}

__global__ void scatter_kernel(const int* __restrict__ src, const int* __restrict__ dst,
                               const int* __restrict__ rid, int* cursor,
                               int* srcs, int* rids, int E) {
    int e = blockIdx.x * blockDim.x + threadIdx.x;
    if (e < E) {
        int p = atomicAdd(&cursor[dst[e]], 1);
        srcs[p] = src[e];
        rids[p] = rid[e];
    }
}

// ---------------- layernorm (warp per row) ----------------
__global__ void ln_kernel(const float* __restrict__ x, const float* __restrict__ g,
                          const float* __restrict__ b, float* __restrict__ y, int nrows) {
    int w = (blockIdx.x * blockDim.x + threadIdx.x) >> 5;
    if (w >= nrows) return;
    int lane = threadIdx.x & 31;
    float4 v = *(const float4*)(x + (long)w * D + lane * 4);
    float s = v.x + v.y + v.z + v.w;
    #pragma unroll
    for (int o = 16; o; o >>= 1) s += __shfl_xor_sync(0xffffffffu, s, o);
    float mean = s * (1.0f / 128.0f);
    float dx = v.x - mean, dy = v.y - mean, dz = v.z - mean, dw = v.w - mean;
    float q = dx * dx + dy * dy + dz * dz + dw * dw;
    #pragma unroll
    for (int o = 16; o; o >>= 1) q += __shfl_xor_sync(0xffffffffu, q, o);
    float inv = rsqrtf(q * (1.0f / 128.0f) + 1e-5f);
    float4 g4 = *(const float4*)(g + lane * 4);
    float4 b4 = *(const float4*)(b + lane * 4);
    float4 o4;
    o4.x = dx * inv * g4.x + b4.x;
    o4.y = dy * inv * g4.y + b4.y;
    o4.z = dz * inv * g4.z + b4.z;
    o4.w = dw * inv * g4.w + b4.w;
    *(float4*)(y + (long)w * D + lane * 4) = o4;
}

// ---------------- tf32 tensor-core GEMM ----------------
__device__ __forceinline__ uint32_t f2tf32(float x) {
    uint32_t r;
    asm("cvt.rna.tf32.f32 %0, %1;" : "=r"(r) : "f"(x));
    return r;
}

__device__ __forceinline__ void mma_tf32(float* c, const uint32_t* a, const uint32_t* b) {
    asm volatile(
        "mma.sync.aligned.m16n8k8.row.col.f32.tf32.tf32.f32 "
        "{%0,%1,%2,%3}, {%4,%5,%6,%7}, {%8,%9}, {%0,%1,%2,%3};\n"
        : "+f"(c[0]), "+f"(c[1]), "+f"(c[2]), "+f"(c[3])
        : "r"(a[0]), "r"(a[1]), "r"(a[2]), "r"(a[3]), "r"(b[0]), "r"(b[1]));
}

// C[M,Nc] = X[M,K] @ W[K,Nc] (+epilogue). Block tile 128x128, BK=32, 256 thr.
// EPI: 0 = none; 1 = relu(acc+bias); 2 = acc + bias + rst
#define MM_SMEM ((2 * 128 * 36 + 2 * 32 * 132) * 4)
template<int EPI, typename Tin, typename Tout>
__global__ void __launch_bounds__(256) mm_tf32_kernel(
    const Tin* __restrict__ X, const float* __restrict__ W,
    const float* __restrict__ bias, const float* __restrict__ rst,
    Tout* __restrict__ Y, int M, int K, int Nc)
{
    extern __shared__ uint32_t smem_u[];
    uint32_t* Abase = smem_u;                // 2 bufs of [128][36]
    uint32_t* Bbase = smem_u + 2 * 128 * 36; // 2 bufs of [32][132]
    const int tid = threadIdx.x;
    const int lane = tid & 31;
    const int warp = tid >> 5;
    const int m_off = (warp & 3) * 32;
    const int n_off = (warp >> 2) * 64;
    const int r0 = blockIdx.x * 128;
    const int n0 = blockIdx.y * 128;

    float acc[2][8][4];
    #pragma unroll
    for (int mi = 0; mi < 2; mi++)
        #pragma unroll
        for (int ni = 0; ni < 8; ni++)
            #pragma unroll
            for (int j = 0; j < 4; j++) acc[mi][ni][j] = 0.0f;

    const int T = K >> 5;
    float4 ra[4], rb[4];

    #pragma unroll
    for (int i = 0; i < 4; i++) {
        int pos = tid + i * 256;
        int row = pos >> 3, c4 = pos & 7;
        int gr = r0 + row;
        ra[i] = (gr < M) ? ld4(X + (long)gr * K + c4 * 4)
                         : make_float4(0.f, 0.f, 0.f, 0.f);
        int brow = pos >> 5, bc4 = pos & 31;
        rb[i] = *(const float4*)(W + (long)brow * Nc + n0 + bc4 * 4);
    }
    {
        uint32_t* As = Abase;
        uint32_t* Bs = Bbase;
        #pragma unroll
        for (int i = 0; i < 4; i++) {
            int pos = tid + i * 256;
            int row = pos >> 3, c4 = pos & 7;
            As[row * 36 + c4 * 4 + 0] = f2tf32(ra[i].x);
            As[row * 36 + c4 * 4 + 1] = f2tf32(ra[i].y);
            As[row * 36 + c4 * 4 + 2] = f2tf32(ra[i].z);
            As[row * 36 + c4 * 4 + 3] = f2tf32(ra[i].w);
            int brow = pos >> 5, bc4 = pos & 31;
            Bs[brow * 132 + bc4 * 4 + 0] = f2tf32(rb[i].x);
            Bs[brow * 132 + bc4 * 4 + 1] = f2tf32(rb[i].y);
            Bs[brow * 132 + bc4 * 4 + 2] = f2tf32(rb[i].z);
            Bs[brow * 132 + bc4 * 4 + 3] = f2tf32(rb[i].w);
        }
    }
    __syncthreads();

    for (int t = 0; t < T; t++) {
        if (t + 1 < T) {
            #pragma unroll
            for (int i = 0; i < 4; i++) {
                int pos = tid + i * 256;
                int row = pos >> 3, c4 = pos & 7;
                int gr = r0 + row;
                int gk = (t + 1) * 32 + c4 * 4;
                ra[i] = (gr < M) ? ld4(X + (long)gr * K + gk)
                                 : make_float4(0.f, 0.f, 0.f, 0.f);
                int brow = pos >> 5, bc4 = pos & 31;
                rb[i] = *(const float4*)(W + (long)((t + 1) * 32 + brow) * Nc + n0 + bc4 * 4);
            }
        }
        uint32_t* As = Abase + (t & 1) * 128 * 36;
        uint32_t* Bs = Bbase + (t & 1) * 32 * 132;
        #pragma unroll
        for (int ks = 0; ks < 4; ks++) {
            int kk = ks * 8 + (lane & 3);
            uint32_t a[2][4];
            #pragma unroll
            for (int mi = 0; mi < 2; mi++) {
                int r = m_off + mi * 16 + (lane >> 2);
                a[mi][0] = As[r * 36 + kk];
                a[mi][1] = As[(r + 8) * 36 + kk];
                a[mi][2] = As[r * 36 + kk + 4];
                a[mi][3] = As[(r + 8) * 36 + kk + 4];
            }
            uint32_t b[8][2];
            #pragma unroll
            for (int ni = 0; ni < 8; ni++) {
                int cc = n_off + ni * 8 + (lane >> 2);
                b[ni][0] = Bs[kk * 132 + cc];
                b[ni][1] = Bs[(kk + 4) * 132 + cc];
            }
            #pragma unroll
            for (int mi = 0; mi < 2; mi++)
                #pragma unroll
                for (int ni = 0; ni < 8; ni++)
                    mma_tf32(acc[mi][ni], a[mi], b[ni]);
        }
        if (t + 1 < T) {
            __syncthreads();
            uint32_t* As2 = Abase + ((t + 1) & 1) * 128 * 36;
            uint32_t* Bs2 = Bbase + ((t + 1) & 1) * 32 * 132;
            #pragma unroll
            for (int i = 0; i < 4; i++) {
                int pos = tid + i * 256;
                int row = pos >> 3, c4 = pos & 7;
                As2[row * 36 + c4 * 4 + 0] = f2tf32(ra[i].x);
                As2[row * 36 + c4 * 4 + 1] = f2tf32(ra[i].y);
                As2[row * 36 + c4 * 4 + 2] = f2tf32(ra[i].z);
                As2[row * 36 + c4 * 4 + 3] = f2tf32(ra[i].w);
                int brow = pos >> 5, bc4 = pos & 31;
                Bs2[brow * 132 + bc4 * 4 + 0] = f2tf32(rb[i].x);
                Bs2[brow * 132 + bc4 * 4 + 1] = f2tf32(rb[i].y);
                Bs2[brow * 132 + bc4 * 4 + 2] = f2tf32(rb[i].z);
                Bs2[brow * 132 + bc4 * 4 + 3] = f2tf32(rb[i].w);
            }
            __syncthreads();
        }
    }

    // epilogue
    #pragma unroll
    for (int mi = 0; mi < 2; mi++) {
        #pragma unroll
        for (int half = 0; half < 2; half++) {
            int row = m_off + mi * 16 + (lane >> 2) + half * 8;
            int gr = r0 + row;
            if (gr >= M) continue;
            #pragma unroll
            for (int ni = 0; ni < 8; ni++) {
                int col = n_off + ni * 8 + (lane & 3) * 2;
                float v0 = acc[mi][ni][half * 2 + 0];
                float v1 = acc[mi][ni][half * 2 + 1];
                if (EPI == 1) {
                    v0 = fmaxf(v0 + bias[n0 + col], 0.0f);
                    v1 = fmaxf(v1 + bias[n0 + col + 1], 0.0f);
                } else if (EPI == 2) {
                    v0 += bias[n0 + col] + rst[(long)gr * Nc + n0 + col];
                    v1 += bias[n0 + col + 1] + rst[(long)gr * Nc + n0 + col + 1];
                }
                st2(Y + (long)gr * Nc + n0 + col, v0, v1);
            }
        }
    }
}

// ---------------- attention (warp per dst node): raw exp + per-node scale ----------------
__global__ void attn_kernel(const int* __restrict__ rowoff, const int* __restrict__ deg,
                            const int* __restrict__ srcs, const int* __restrict__ rids,
                            const __half* __restrict__ kb, const float* __restrict__ qb,
                            const float* __restrict__ relp, float* __restrict__ ex,
                            float* __restrict__ nscale, int N) {
    int w = (blockIdx.x * blockDim.x + threadIdx.x) >> 5;
    if (w >= N) return;
    int lane = threadIdx.x & 31;
    int head4 = lane >> 2;
    int start = rowoff[w];
    int dg = deg[w];
    float4 q4 = *(const float4*)(qb + (long)w * D + lane * 4);
    float c = log1pf((float)dg) * 0.25f;  // log_in / sqrt(DH)
    float sum = 0.0f;
    int s_cur = 0, r_cur = 0;
    if (dg > 0) { s_cur = srcs[start]; r_cur = rids[start]; }
    for (int i = 0; i < dg; i++) {
        int s_nxt = 0, r_nxt = 0;
        if (i + 1 < dg) { s_nxt = srcs[start + i + 1]; r_nxt = rids[start + i + 1]; }
        float4 k4 = ld4(kb + (long)s_cur * D + lane * 4);
        float4 r4 = *(const float4*)(relp + (long)r_cur * D + lane * 4);
        float part = k4.x * r4.x * q4.x + k4.y * r4.y * q4.y +
                     k4.z * r4.z * q4.z + k4.w * r4.w * q4.w;
        part += __shfl_xor_sync(0xffffffffu, part, 1);
        part += __shfl_xor_sync(0xffffffffu, part, 2);
        // logits are small (|.| < ~10): exp without max-subtraction is exact
        // for the softmax ratio and cannot overflow.
        float e = __expf(part * c);
        if ((lane & 3) == 0) ex[(long)(start + i) * H + head4] = e;
        sum += e;
        s_cur = s_nxt; r_cur = r_nxt;
    }
    float s_h = __shfl_sync(0xffffffffu, sum, (lane & 7) * 4);
    if (lane < 8)
        nscale[(long)w * H + lane] = (s_h > 0.0f) ? ((1.0f - ALPHA) / s_h) : 0.0f;
}

// ---------------- PPR diffusion hop (warp per dst node, fp16 feats) ----------------
__global__ void hop_kernel(const int* __restrict__ rowoff, const int* __restrict__ deg,
                           const int* __restrict__ srcs, const float* __restrict__ ex,
                           const float* __restrict__ nscale,
                           const __half* __restrict__ fin, const __half* __restrict__ f0,
                           __half* __restrict__ fout, int N) {
    int w = (blockIdx.x * blockDim.x + threadIdx.x) >> 5;
    if (w >= N) return;
    int lane = threadIdx.x & 31;
    int head = lane >> 2;
    int start = rowoff[w];
    int dg = deg[w];
    float4 acc = make_float4(0.f, 0.f, 0.f, 0.f);
    int s_cur = 0; float e_cur = 0.f;
    if (dg > 0) { s_cur = srcs[start]; e_cur = ex[(long)start * H + head]; }
    for (int i = 0; i < dg; i++) {
        int s_nxt = 0; float e_nxt = 0.f;
        if (i + 1 < dg) {
            s_nxt = srcs[start + i + 1];
            e_nxt = ex[(long)(start + i + 1) * H + head];
        }
        float4 f = ld4(fin + (long)s_cur * D + lane * 4);
        acc.x += e_cur * f.x;
        acc.y += e_cur * f.y;
        acc.z += e_cur * f.z;
        acc.w += e_cur * f.w;
        s_cur = s_nxt; e_cur = e_nxt;
    }
    float sc = nscale[(long)w * H + head];
    float4 z = ld4(f0 + (long)w * D + lane * 4);
    acc.x = acc.x * sc + ALPHA * z.x;
    acc.y = acc.y * sc + ALPHA * z.y;
    acc.z = acc.z * sc + ALPHA * z.z;
    acc.w = acc.w * sc + ALPHA * z.w;
    float2 pk;
    ((__half2*)&pk)[0] = __floats2half2_rn(acc.x, acc.y);
    ((__half2*)&pk)[1] = __floats2half2_rn(acc.z, acc.w);
    *(float2*)(fout + (long)w * D + lane * 4) = pk;
}

// ---------------- last hop fused with residual + LN (fp32 result, no rounding) ----------------
__global__ void hop_last_kernel(const int* __restrict__ rowoff, const int* __restrict__ deg,
                                const int* __restrict__ srcs, const float* __restrict__ ex,
                                const float* __restrict__ nscale,
                                const __half* __restrict__ fin, const __half* __restrict__ f0,
                                const float* __restrict__ ent,
                                const float* __restrict__ g, const float* __restrict__ b,
                                float* __restrict__ y, float* __restrict__ rst, int N) {
    int w = (blockIdx.x * blockDim.x + threadIdx.x) >> 5;
    if (w >= N) return;
    int lane = threadIdx.x & 31;
    int head = lane >> 2;
    int start = rowoff[w];
    int dg = deg[w];
    float4 acc = make_float4(0.f, 0.f, 0.f, 0.f);
    int s_cur = 0; float e_cur = 0.f;
    if (dg > 0) { s_cur = srcs[start]; e_cur = ex[(long)start * H + head]; }
    for (int i = 0; i < dg; i++) {
        int s_nxt = 0; float e_nxt = 0.f;
        if (i + 1 < dg) {
            s_nxt = srcs[start + i + 1];
            e_nxt = ex[(long)(start + i + 1) * H + head];
        }
        float4 f = ld4(fin + (long)s_cur * D + lane * 4);
        acc.x += e_cur * f.x;
        acc.y += e_cur * f.y;
        acc.z += e_cur * f.z;
        acc.w += e_cur * f.w;
        s_cur = s_nxt; e_cur = e_nxt;
    }
    float sc = nscale[(long)w * H + head];
    float4 z = ld4(f0 + (long)w * D + lane * 4);
    float4 e4 = *(const float4*)(ent + (long)w * D + lane * 4);
    float4 v;
    v.x = acc.x * sc + ALPHA * z.x + e4.x;
    v.y = acc.y * sc + ALPHA * z.y + e4.y;
    v.z = acc.z * sc + ALPHA * z.z + e4.z;
    v.w = acc.w * sc + ALPHA * z.w + e4.w;
    *(float4*)(rst + (long)w * D + lane * 4) = v;
    // warp layernorm over the 128-dim row
    float s = v.x + v.y + v.z + v.w;
    #pragma unroll
    for (int o = 16; o; o >>= 1) s += __shfl_xor_sync(0xffffffffu, s, o);
    float mean = s * (1.0f / 128.0f);
    float dx = v.x - mean, dy = v.y - mean, dz = v.z - mean, dw = v.w - mean;
    float q = dx * dx + dy * dy + dz * dz + dw * dw;
    #pragma unroll
    for (int o = 16; o; o >>= 1) q += __shfl_xor_sync(0xffffffffu, q, o);
    float inv = rsqrtf(q * (1.0f / 128.0f) + 1e-5f);
    float4 g4 = *(const float4*)(g + lane * 4);
    float4 b4 = *(const float4*)(b + lane * 4);
    float4 o4;
    o4.x = dx * inv * g4.x + b4.x;
    o4.y = dy * inv * g4.y + b4.y;
    o4.z = dz * inv * g4.z + b4.z;
    o4.w = dw * inv * g4.w + b4.w;
    *(float4*)(y + (long)w * D + lane * 4) = o4;
}

// ---------------- launch ----------------
extern "C" void kernel_launch(void* const* d_in, const int* in_sizes, int n_in,
                              void* d_out, int out_size) {
    const float* ent    = (const float*)d_in[0];
    const float* relf   = (const float*)d_in[1];
    const float* W_head = (const float*)d_in[2];
    const float* W_tail = (const float*)d_in[3];
    const float* W_ent  = (const float*)d_in[4];
    const float* W_rel  = (const float*)d_in[5];
    const float* g_ent  = (const float*)d_in[6];
    const float* b_ent  = (const float*)d_in[7];
    const float* g_rel  = (const float*)d_in[8];
    const float* b_rel  = (const float*)d_in[9];
    const float* g_ff   = (const float*)d_in[10];
    const float* b_ff   = (const float*)d_in[11];
    const float* W1     = (const float*)d_in[12];
    const float* b1     = (const float*)d_in[13];
    const float* W2     = (const float*)d_in[14];
    const float* b2     = (const float*)d_in[15];
    const int*   src    = (const int*)d_in[16];
    const int*   dst    = (const int*)d_in[17];
    const int*   rid    = (const int*)d_in[18];
    float* out = (float*)d_out;

    int N = in_sizes[0] / D;
    int R = in_sizes[1] / D;
    int E = in_sizes[16];

    float *p_xn, *p_q, *p_ex, *p_nscale, *p_relx, *p_relp;
    __half *p_kh, *p_vh, *p_fA, *p_fB, *p_hh;
    int *p_deg, *p_rowoff, *p_cursor, *p_srcs, *p_rids, *p_bsums;
    cudaGetSymbolAddress((void**)&p_xn, d_xn);
    cudaGetSymbolAddress((void**)&p_q, d_q);
    cudaGetSymbolAddress((void**)&p_kh, d_kh);
    cudaGetSymbolAddress((void**)&p_vh, d_vh);
    cudaGetSymbolAddress((void**)&p_fA, d_fA);
    cudaGetSymbolAddress((void**)&p_fB, d_fB);
    cudaGetSymbolAddress((void**)&p_hh, d_hh);
    cudaGetSymbolAddress((void**)&p_ex, d_ex);
    cudaGetSymbolAddress((void**)&p_nscale, d_nscale);
    cudaGetSymbolAddress((void**)&p_relx, d_relx);
    cudaGetSymbolAddress((void**)&p_relp, d_relp);
    cudaGetSymbolAddress((void**)&p_deg, d_deg);
    cudaGetSymbolAddress((void**)&p_rowoff, d_rowoff);
    cudaGetSymbolAddress((void**)&p_cursor, d_cursor);
    cudaGetSymbolAddress((void**)&p_srcs, d_srcs);
    cudaGetSymbolAddress((void**)&p_rids, d_rids);
    cudaGetSymbolAddress((void**)&p_bsums, d_bsums);

    cudaFuncSetAttribute((const void*)mm_tf32_kernel<0, float, float>,
                         cudaFuncAttributeMaxDynamicSharedMemorySize, MM_SMEM);
    cudaFuncSetAttribute((const void*)mm_tf32_kernel<0, float, __half>,
                         cudaFuncAttributeMaxDynamicSharedMemorySize, MM_SMEM);
    cudaFuncSetAttribute((const void*)mm_tf32_kernel<1, float, __half>,
                         cudaFuncAttributeMaxDynamicSharedMemorySize, MM_SMEM);
    cudaFuncSetAttribute((const void*)mm_tf32_kernel<2, __half, float>,
                         cudaFuncAttributeMaxDynamicSharedMemorySize, MM_SMEM);

    int nb = (N + 1023) / 1024;
    int mblocks = (N + 127) / 128;

    // projections first (launch index 5 == big proj GEMM for the ncu window)
    ln_kernel<<<(N + 7) / 8, 256>>>(ent, g_ent, b_ent, p_xn, N);                         // 0
    ln_kernel<<<(R + 7) / 8, 256>>>(relf, g_rel, b_rel, p_relx, R);                      // 1
    mm_tf32_kernel<0, float, float><<<dim3(1, 1), 256, MM_SMEM>>>(
        p_relx, W_rel, nullptr, nullptr, p_relp, R, 128, 128);                           // 2
    mm_tf32_kernel<0, float, __half><<<dim3(mblocks, 1), 256, MM_SMEM>>>(
        p_xn, W_head, nullptr, nullptr, p_kh, N, 128, 128);                              // 3
    mm_tf32_kernel<0, float, float><<<dim3(mblocks, 1), 256, MM_SMEM>>>(
        p_xn, W_tail, nullptr, nullptr, p_q, N, 128, 128);                               // 4
    mm_tf32_kernel<0, float, __half><<<dim3(mblocks, 1), 256, MM_SMEM>>>(
        p_xn, W_ent, nullptr, nullptr, p_vh, N, 128, 128);                               // 5 <- profiled

    // CSR build
    zero_deg_kernel<<<(N + 255) / 256, 256>>>(p_deg, N);
    hist_kernel<<<(E + 255) / 256, 256>>>(dst, p_deg, E);
    scan1_kernel<<<nb, 1024>>>(p_deg, p_rowoff, p_bsums, N);
    scan2_kernel<<<1, 256>>>(p_bsums, nb);
    scan3_kernel<<<(N + 255) / 256, 256>>>(p_rowoff, p_cursor, p_bsums, N);
    scatter_kernel<<<(E + 255) / 256, 256>>>(src, dst, rid, p_cursor, p_srcs, p_rids, E);

    // attention: raw exp + per-node (1-alpha)/sum
    attn_kernel<<<(N + 7) / 8, 256>>>(p_rowoff, p_deg, p_srcs, p_rids,
                                      p_kh, p_q, p_relp, p_ex, p_nscale, N);

    // PPR hops: v -> A -> B -> A -> (fused last: y, rst)
    hop_kernel<<<(N + 7) / 8, 256>>>(p_rowoff, p_deg, p_srcs, p_ex, p_nscale,
                                     p_vh, p_vh, p_fA, N);
    hop_kernel<<<(N + 7) / 8, 256>>>(p_rowoff, p_deg, p_srcs, p_ex, p_nscale,
                                     p_fA, p_vh, p_fB, N);
    hop_kernel<<<(N + 7) / 8, 256>>>(p_rowoff, p_deg, p_srcs, p_ex, p_nscale,
                                     p_fB, p_vh, p_fA, N);
    hop_last_kernel<<<(N + 7) / 8, 256>>>(p_rowoff, p_deg, p_srcs, p_ex, p_nscale,
                                          p_fA, p_vh, ent, g_ff, b_ff,
                                          p_xn, p_q, N);   // y -> d_xn, rst -> d_q

    // FFN: h = relu(y@W1+b1) in fp16; out = h@W2 + b2 + rst
    mm_tf32_kernel<1, float, __half><<<dim3(mblocks, 4), 256, MM_SMEM>>>(
        p_xn, W1, b1, nullptr, p_hh, N, 128, 512);
    mm_tf32_kernel<2, __half, float><<<dim3(mblocks, 1), 256, MM_SMEM>>>(
        p_hh, W2, b2, p_q, out, N, 512, 128);
}

// round 4
// speedup vs baseline: 2.6680x; 1.3865x over previous
#include <cuda_runtime.h>
#include <cuda_fp16.h>
#include <math.h>
#include <stdint.h>

#define D 128
#define H 8
#define NMAX 100000
#define EMAX 1600000
#define RMAX 128
#define ALPHA 0.1f

// ---------------- scratch (device globals; no allocations) ----------------
__device__ __half d_xnh[NMAX * D];    // LN(ent) fp16; later y = LN(rst) fp16
__device__ float  d_q[NMAX * D];      // q projection fp32; later rst fp32
__device__ __half d_kh[NMAX * D];
__device__ __half d_vh[NMAX * D];
__device__ __half d_fA[NMAX * D];
__device__ __half d_fB[NMAX * D];
__device__ __half d_hh[NMAX * 512];
__device__ float  d_ex[EMAX * H];
__device__ float  d_nscale[NMAX * H];
__device__ __half d_relxh[RMAX * D];
__device__ float  d_relp[RMAX * D];
__device__ __half d_w16[4 * 16384 + 2 * 65536];
__device__ int    d_deg[NMAX];
__device__ int    d_rowoff[NMAX];
__device__ int    d_cursor[NMAX];
__device__ int    d_srcs[EMAX];
__device__ int    d_rids[EMAX];
__device__ int    d_bsums[256];

#define OFF_WH 0
#define OFF_WT 16384
#define OFF_WE 32768
#define OFF_WR 49152
#define OFF_W1 65536
#define OFF_W2 131072

// ---------------- typed helpers ----------------
__device__ __forceinline__ float4 ld4(const float* p) { return *(const float4*)p; }
__device__ __forceinline__ float4 ld4(const __half* p) {
    float2 r = *(const float2*)p;
    __half2 h0 = ((const __half2*)&r)[0];
    __half2 h1 = ((const __half2*)&r)[1];
    float2 a = __half22float2(h0), b = __half22float2(h1);
    return make_float4(a.x, a.y, b.x, b.y);
}
__device__ __forceinline__ void st2(float* p, float a, float b) {
    *(float2*)p = make_float2(a, b);
}
__device__ __forceinline__ void st2(__half* p, float a, float b) {
    *(__half2*)p = __floats2half2_rn(a, b);
}
__device__ __forceinline__ uint32_t smem_u32(const void* p) {
    return (uint32_t)__cvta_generic_to_shared(p);
}
__device__ __forceinline__ void cp_async16(uint32_t dst, const void* src, bool pred) {
    int sz = pred ? 16 : 0;
    asm volatile("cp.async.cg.shared.global [%0], [%1], 16, %2;\n"
                 :: "r"(dst), "l"(src), "r"(sz));
}
__device__ __forceinline__ void ldsm4(uint32_t* r, uint32_t addr) {
    asm volatile("ldmatrix.sync.aligned.m8n8.x4.shared.b16 {%0,%1,%2,%3}, [%4];"
                 : "=r"(r[0]), "=r"(r[1]), "=r"(r[2]), "=r"(r[3]) : "r"(addr));
}
__device__ __forceinline__ void ldsm4t(uint32_t* r, uint32_t addr) {
    asm volatile("ldmatrix.sync.aligned.m8n8.x4.trans.shared.b16 {%0,%1,%2,%3}, [%4];"
                 : "=r"(r[0]), "=r"(r[1]), "=r"(r[2]), "=r"(r[3]) : "r"(addr));
}
__device__ __forceinline__ void mma_f16(float* c, const uint32_t* a, const uint32_t* b) {
    asm volatile(
        "mma.sync.aligned.m16n8k16.row.col.f32.f16.f16.f32 "
        "{%0,%1,%2,%3}, {%4,%5,%6,%7}, {%8,%9}, {%0,%1,%2,%3};\n"
        : "+f"(c[0]), "+f"(c[1]), "+f"(c[2]), "+f"(c[3])
        : "r"(a[0]), "r"(a[1]), "r"(a[2]), "r"(a[3]), "r"(b[0]), "r"(b[1]));
}

// ---------------- weight convert (one launch) ----------------
__global__ void cvt_weights(const float* __restrict__ wh, const float* __restrict__ wt,
                            const float* __restrict__ we, const float* __restrict__ wr,
                            const float* __restrict__ w1, const float* __restrict__ w2,
                            __half* __restrict__ out) {
    int base = (blockIdx.x * blockDim.x + threadIdx.x) * 4;
    const float* src; int off;
    if (base < 16384)       { src = wh; off = OFF_WH; }
    else if (base < 32768)  { src = wt; off = OFF_WT; }
    else if (base < 49152)  { src = we; off = OFF_WE; }
    else if (base < 65536)  { src = wr; off = OFF_WR; }
    else if (base < 131072) { src = w1; off = OFF_W1; }
    else                    { src = w2; off = OFF_W2; }
    float4 v = *(const float4*)(src + base - off);
    __half2* o = (__half2*)(out + base);
    o[0] = __floats2half2_rn(v.x, v.y);
    o[1] = __floats2half2_rn(v.z, v.w);
}

// ---------------- CSR build ----------------
__global__ void zero_deg_kernel(int* deg, int n) {
    int i = blockIdx.x * blockDim.x + threadIdx.x;
    if (i < n) deg[i] = 0;
}

__global__ void hist_kernel(const int* __restrict__ dst, int* deg, int E) {
    int e = blockIdx.x * blockDim.x + threadIdx.x;
    if (e < E) atomicAdd(&deg[dst[e]], 1);
}

__global__ void scan1_kernel(const int* __restrict__ deg, int* rowoff, int* bsums, int n) {
    __shared__ int sh[1024];
    int i = blockIdx.x * 1024 + threadIdx.x;
    int v = (i < n) ? deg[i] : 0;
    sh[threadIdx.x] = v;
    __syncthreads();
    for (int off = 1; off < 1024; off <<= 1) {
        int t = (threadIdx.x >= off) ? sh[threadIdx.x - off] : 0;
        __syncthreads();
        sh[threadIdx.x] += t;
        __syncthreads();
    }
    if (i < n) rowoff[i] = sh[threadIdx.x] - v;  // exclusive
    if (threadIdx.x == 1023) bsums[blockIdx.x] = sh[1023];
}

__global__ void scan2_kernel(int* bsums, int nb) {
    __shared__ int sh[256];
    int v = (threadIdx.x < nb) ? bsums[threadIdx.x] : 0;
    sh[threadIdx.x] = v;
    __syncthreads();
    for (int off = 1; off < 256; off <<= 1) {
        int t = (threadIdx.x >= off) ? sh[threadIdx.x - off] : 0;
        __syncthreads();
        sh[threadIdx.x] += t;
        __syncthreads();
    }
    if (threadIdx.x < nb) bsums[threadIdx.x] = sh[threadIdx.x] - v;  // exclusive
}

__global__ void scan3_kernel(int* rowoff, int* cursor, const int* __restrict__ bsums, int n) {
    int i = blockIdx.x * blockDim.x + threadIdx.x;
    if (i < n) {
        int r = rowoff[i] + bsums[i >> 10];
        rowoff[i] = r;
        cursor[i] = r;
    }
}

__global__ void scatter_kernel(const int* __restrict__ src, const int* __restrict__ dst,
                               const int* __restrict__ rid, int* cursor,
                               int* srcs, int* rids, int E) {
    int e = blockIdx.x * blockDim.x + threadIdx.x;
    if (e < E) {
        int p = atomicAdd(&cursor[dst[e]], 1);
        srcs[p] = src[e];
        rids[p] = rid[e];
    }
}

// ---------------- layernorm (warp per row), templated output ----------------
template<typename Tout>
__global__ void ln_kernel(const float* __restrict__ x, const float* __restrict__ g,
                          const float* __restrict__ b, Tout* __restrict__ y, int nrows) {
    int w = (blockIdx.x * blockDim.x + threadIdx.x) >> 5;
    if (w >= nrows) return;
    int lane = threadIdx.x & 31;
    float4 v = *(const float4*)(x + (long)w * D + lane * 4);
    float s = v.x + v.y + v.z + v.w;
    #pragma unroll
    for (int o = 16; o; o >>= 1) s += __shfl_xor_sync(0xffffffffu, s, o);
    float mean = s * (1.0f / 128.0f);
    float dx = v.x - mean, dy = v.y - mean, dz = v.z - mean, dw = v.w - mean;
    float q = dx * dx + dy * dy + dz * dz + dw * dw;
    #pragma unroll
    for (int o = 16; o; o >>= 1) q += __shfl_xor_sync(0xffffffffu, q, o);
    float inv = rsqrtf(q * (1.0f / 128.0f) + 1e-5f);
    float4 g4 = *(const float4*)(g + lane * 4);
    float4 b4 = *(const float4*)(b + lane * 4);
    st2(y + (long)w * D + lane * 4,     dx * inv * g4.x + b4.x, dy * inv * g4.y + b4.y);
    st2(y + (long)w * D + lane * 4 + 2, dz * inv * g4.z + b4.z, dw * inv * g4.w + b4.w);
}

// ---------------- fp16 tensor-core GEMM: C[M,Nc] = X[M,K] @ W[K,Nc] ----------------
// Block tile 128x128, BK=32, 256 threads, cp.async double buffer, ldmatrix frags.
// EPI: 0 = none; 1 = relu(acc+bias); 2 = acc + bias + rst
#define AS_STRIDE 40
#define BS_STRIDE 136
template<int EPI, typename Tout>
__global__ void __launch_bounds__(256, 2) mm_f16_kernel(
    const __half* __restrict__ X, const __half* __restrict__ W,
    const float* __restrict__ bias, const float* __restrict__ rst,
    Tout* __restrict__ Y, int M, int K, int Nc)
{
    __shared__ __half As[2][128 * AS_STRIDE];
    __shared__ __half Bs[2][32 * BS_STRIDE];
    const int tid = threadIdx.x;
    const int lane = tid & 31;
    const int warp = tid >> 5;
    const int m_off = (warp & 3) * 32;
    const int n_off = (warp >> 2) * 64;
    const int r0 = blockIdx.x * 128;
    const int n0 = blockIdx.y * 128;

    float acc[2][8][4];
    #pragma unroll
    for (int mi = 0; mi < 2; mi++)
        #pragma unroll
        for (int ni = 0; ni < 8; ni++)
            #pragma unroll
            for (int j = 0; j < 4; j++) acc[mi][ni][j] = 0.0f;

    const int T = K >> 5;

    auto issue = [&](int t, int bf) {
        #pragma unroll
        for (int i = 0; i < 2; i++) {
            int ci = tid + i * 256;
            int row = ci >> 2, kc = (ci & 3) * 8;
            int gr = r0 + row;
            cp_async16(smem_u32(&As[bf][row * AS_STRIDE + kc]),
                       X + (long)gr * K + t * 32 + kc, gr < M);
            int brow = ci >> 4, nc = (ci & 15) * 8;
            cp_async16(smem_u32(&Bs[bf][brow * BS_STRIDE + nc]),
                       W + (long)(t * 32 + brow) * Nc + n0 + nc, true);
        }
        asm volatile("cp.async.commit_group;\n" ::);
    };

    issue(0, 0);
    for (int t = 0; t < T; t++) {
        if (t + 1 < T) {
            issue(t + 1, (t + 1) & 1);
            asm volatile("cp.async.wait_group 1;\n" ::);
        } else {
            asm volatile("cp.async.wait_group 0;\n" ::);
        }
        __syncthreads();
        const __half* A = As[t & 1];
        const __half* B = Bs[t & 1];
        #pragma unroll
        for (int ks = 0; ks < 2; ks++) {
            uint32_t a[2][4];
            #pragma unroll
            for (int mi = 0; mi < 2; mi++) {
                int m = m_off + mi * 16 + (lane & 7) + (lane & 8);
                int k = ks * 16 + ((lane >> 4) << 3);
                ldsm4(a[mi], smem_u32(&A[m * AS_STRIDE + k]));
            }
            uint32_t b[8][2];
            #pragma unroll
            for (int nb = 0; nb < 4; nb++) {
                uint32_t r[4];
                int k = ks * 16 + (lane & 7) + (lane & 8);
                int n = n_off + nb * 16 + ((lane >> 4) << 3);
                ldsm4t(r, smem_u32(&B[k * BS_STRIDE + n]));
                b[nb * 2][0] = r[0]; b[nb * 2][1] = r[1];
                b[nb * 2 + 1][0] = r[2]; b[nb * 2 + 1][1] = r[3];
            }
            #pragma unroll
            for (int mi = 0; mi < 2; mi++)
                #pragma unroll
                for (int ni = 0; ni < 8; ni++)
                    mma_f16(acc[mi][ni], a[mi], b[ni]);
        }
        __syncthreads();
    }

    // epilogue
    #pragma unroll
    for (int mi = 0; mi < 2; mi++) {
        #pragma unroll
        for (int half = 0; half < 2; half++) {
            int row = m_off + mi * 16 + (lane >> 2) + half * 8;
            int gr = r0 + row;
            if (gr >= M) continue;
            #pragma unroll
            for (int ni = 0; ni < 8; ni++) {
                int col = n_off + ni * 8 + (lane & 3) * 2;
                float v0 = acc[mi][ni][half * 2 + 0];
                float v1 = acc[mi][ni][half * 2 + 1];
                if (EPI == 1) {
                    v0 = fmaxf(v0 + bias[n0 + col], 0.0f);
                    v1 = fmaxf(v1 + bias[n0 + col + 1], 0.0f);
                } else if (EPI == 2) {
                    v0 += bias[n0 + col] + rst[(long)gr * Nc + n0 + col];
                    v1 += bias[n0 + col + 1] + rst[(long)gr * Nc + n0 + col + 1];
                }
                st2(Y + (long)gr * Nc + n0 + col, v0, v1);
            }
        }
    }
}

// ---------------- attention (warp per dst node): raw exp + per-node scale ----------------
__global__ void attn_kernel(const int* __restrict__ rowoff, const int* __restrict__ deg,
                            const int* __restrict__ srcs, const int* __restrict__ rids,
                            const __half* __restrict__ kb, const float* __restrict__ qb,
                            const float* __restrict__ relp, float* __restrict__ ex,
                            float* __restrict__ nscale, int N) {
    int w = (blockIdx.x * blockDim.x + threadIdx.x) >> 5;
    if (w >= N) return;
    int lane = threadIdx.x & 31;
    int head4 = lane >> 2;
    int start = rowoff[w];
    int dg = deg[w];
    float4 q4 = *(const float4*)(qb + (long)w * D + lane * 4);
    float c = log1pf((float)dg) * 0.25f;  // log_in / sqrt(DH)
    float sum = 0.0f;
    int s_cur = 0, r_cur = 0;
    if (dg > 0) { s_cur = srcs[start]; r_cur = rids[start]; }
    for (int i = 0; i < dg; i++) {
        int s_nxt = 0, r_nxt = 0;
        if (i + 1 < dg) { s_nxt = srcs[start + i + 1]; r_nxt = rids[start + i + 1]; }
        float4 k4 = ld4(kb + (long)s_cur * D + lane * 4);
        float4 r4 = *(const float4*)(relp + (long)r_cur * D + lane * 4);
        float part = k4.x * r4.x * q4.x + k4.y * r4.y * q4.y +
                     k4.z * r4.z * q4.z + k4.w * r4.w * q4.w;
        part += __shfl_xor_sync(0xffffffffu, part, 1);
        part += __shfl_xor_sync(0xffffffffu, part, 2);
        float e = __expf(part * c);   // logits tiny: no max-subtraction needed
        if ((lane & 3) == 0) ex[(long)(start + i) * H + head4] = e;
        sum += e;
        s_cur = s_nxt; r_cur = r_nxt;
    }
    float s_h = __shfl_sync(0xffffffffu, sum, (lane & 7) * 4);
    if (lane < 8)
        nscale[(long)w * H + lane] = (s_h > 0.0f) ? ((1.0f - ALPHA) / s_h) : 0.0f;
}

// ---------------- PPR diffusion hop (warp per dst node, fp16 feats) ----------------
__global__ void hop_kernel(const int* __restrict__ rowoff, const int* __restrict__ deg,
                           const int* __restrict__ srcs, const float* __restrict__ ex,
                           const float* __restrict__ nscale,
                           const __half* __restrict__ fin, const __half* __restrict__ f0,
                           __half* __restrict__ fout, int N) {
    int w = (blockIdx.x * blockDim.x + threadIdx.x) >> 5;
    if (w >= N) return;
    int lane = threadIdx.x & 31;
    int head = lane >> 2;
    int start = rowoff[w];
    int dg = deg[w];
    float4 acc = make_float4(0.f, 0.f, 0.f, 0.f);
    int s_cur = 0; float e_cur = 0.f;
    if (dg > 0) { s_cur = srcs[start]; e_cur = ex[(long)start * H + head]; }
    for (int i = 0; i < dg; i++) {
        int s_nxt = 0; float e_nxt = 0.f;
        if (i + 1 < dg) {
            s_nxt = srcs[start + i + 1];
            e_nxt = ex[(long)(start + i + 1) * H + head];
        }
        float4 f = ld4(fin + (long)s_cur * D + lane * 4);
        acc.x += e_cur * f.x;
        acc.y += e_cur * f.y;
        acc.z += e_cur * f.z;
        acc.w += e_cur * f.w;
        s_cur = s_nxt; e_cur = e_nxt;
    }
    float sc = nscale[(long)w * H + head];
    float4 z = ld4(f0 + (long)w * D + lane * 4);
    acc.x = acc.x * sc + ALPHA * z.x;
    acc.y = acc.y * sc + ALPHA * z.y;
    acc.z = acc.z * sc + ALPHA * z.z;
    acc.w = acc.w * sc + ALPHA * z.w;
    float2 pk;
    ((__half2*)&pk)[0] = __floats2half2_rn(acc.x, acc.y);
    ((__half2*)&pk)[1] = __floats2half2_rn(acc.z, acc.w);
    *(float2*)(fout + (long)w * D + lane * 4) = pk;
}

// ---------------- last hop fused with residual + LN ----------------
__global__ void hop_last_kernel(const int* __restrict__ rowoff, const int* __restrict__ deg,
                                const int* __restrict__ srcs, const float* __restrict__ ex,
                                const float* __restrict__ nscale,
                                const __half* __restrict__ fin, const __half* __restrict__ f0,
                                const float* __restrict__ ent,
                                const float* __restrict__ g, const float* __restrict__ b,
                                __half* __restrict__ y, float* __restrict__ rst, int N) {
    int w = (blockIdx.x * blockDim.x + threadIdx.x) >> 5;
    if (w >= N) return;
    int lane = threadIdx.x & 31;
    int head = lane >> 2;
    int start = rowoff[w];
    int dg = deg[w];
    float4 acc = make_float4(0.f, 0.f, 0.f, 0.f);
    int s_cur = 0; float e_cur = 0.f;
    if (dg > 0) { s_cur = srcs[start]; e_cur = ex[(long)start * H + head]; }
    for (int i = 0; i < dg; i++) {
        int s_nxt = 0; float e_nxt = 0.f;
        if (i + 1 < dg) {
            s_nxt = srcs[start + i + 1];
            e_nxt = ex[(long)(start + i + 1) * H + head];
        }
        float4 f = ld4(fin + (long)s_cur * D + lane * 4);
        acc.x += e_cur * f.x;
        acc.y += e_cur * f.y;
        acc.z += e_cur * f.z;
        acc.w += e_cur * f.w;
        s_cur = s_nxt; e_cur = e_nxt;
    }
    float sc = nscale[(long)w * H + head];
    float4 z = ld4(f0 + (long)w * D + lane * 4);
    float4 e4 = *(const float4*)(ent + (long)w * D + lane * 4);
    float4 v;
    v.x = acc.x * sc + ALPHA * z.x + e4.x;
    v.y = acc.y * sc + ALPHA * z.y + e4.y;
    v.z = acc.z * sc + ALPHA * z.z + e4.z;
    v.w = acc.w * sc + ALPHA * z.w + e4.w;
    *(float4*)(rst + (long)w * D + lane * 4) = v;
    float s = v.x + v.y + v.z + v.w;
    #pragma unroll
    for (int o = 16; o; o >>= 1) s += __shfl_xor_sync(0xffffffffu, s, o);
    float mean = s * (1.0f / 128.0f);
    float dx = v.x - mean, dy = v.y - mean, dz = v.z - mean, dw = v.w - mean;
    float q = dx * dx + dy * dy + dz * dz + dw * dw;
    #pragma unroll
    for (int o = 16; o; o >>= 1) q += __shfl_xor_sync(0xffffffffu, q, o);
    float inv = rsqrtf(q * (1.0f / 128.0f) + 1e-5f);
    float4 g4 = *(const float4*)(g + lane * 4);
    float4 b4 = *(const float4*)(b + lane * 4);
    st2(y + (long)w * D + lane * 4,     dx * inv * g4.x + b4.x, dy * inv * g4.y + b4.y);
    st2(y + (long)w * D + lane * 4 + 2, dz * inv * g4.z + b4.z, dw * inv * g4.w + b4.w);
}

// ---------------- launch ----------------
extern "C" void kernel_launch(void* const* d_in, const int* in_sizes, int n_in,
                              void* d_out, int out_size) {
    const float* ent    = (const float*)d_in[0];
    const float* relf   = (const float*)d_in[1];
    const float* W_head = (const float*)d_in[2];
    const float* W_tail = (const float*)d_in[3];
    const float* W_ent  = (const float*)d_in[4];
    const float* W_rel  = (const float*)d_in[5];
    const float* g_ent  = (const float*)d_in[6];
    const float* b_ent  = (const float*)d_in[7];
    const float* g_rel  = (const float*)d_in[8];
    const float* b_rel  = (const float*)d_in[9];
    const float* g_ff   = (const float*)d_in[10];
    const float* b_ff   = (const float*)d_in[11];
    const float* W1     = (const float*)d_in[12];
    const float* b1     = (const float*)d_in[13];
    const float* W2     = (const float*)d_in[14];
    const float* b2     = (const float*)d_in[15];
    const int*   src    = (const int*)d_in[16];
    const int*   dst    = (const int*)d_in[17];
    const int*   rid    = (const int*)d_in[18];
    float* out = (float*)d_out;

    int N = in_sizes[0] / D;
    int R = in_sizes[1] / D;
    int E = in_sizes[16];

    float *p_q, *p_ex, *p_nscale, *p_relp;
    __half *p_xnh, *p_kh, *p_vh, *p_fA, *p_fB, *p_hh, *p_relxh, *p_w16;
    int *p_deg, *p_rowoff, *p_cursor, *p_srcs, *p_rids, *p_bsums;
    cudaGetSymbolAddress((void**)&p_xnh, d_xnh);
    cudaGetSymbolAddress((void**)&p_q, d_q);
    cudaGetSymbolAddress((void**)&p_kh, d_kh);
    cudaGetSymbolAddress((void**)&p_vh, d_vh);
    cudaGetSymbolAddress((void**)&p_fA, d_fA);
    cudaGetSymbolAddress((void**)&p_fB, d_fB);
    cudaGetSymbolAddress((void**)&p_hh, d_hh);
    cudaGetSymbolAddress((void**)&p_ex, d_ex);
    cudaGetSymbolAddress((void**)&p_nscale, d_nscale);
    cudaGetSymbolAddress((void**)&p_relxh, d_relxh);
    cudaGetSymbolAddress((void**)&p_relp, d_relp);
    cudaGetSymbolAddress((void**)&p_w16, d_w16);
    cudaGetSymbolAddress((void**)&p_deg, d_deg);
    cudaGetSymbolAddress((void**)&p_rowoff, d_rowoff);
    cudaGetSymbolAddress((void**)&p_cursor, d_cursor);
    cudaGetSymbolAddress((void**)&p_srcs, d_srcs);
    cudaGetSymbolAddress((void**)&p_rids, d_rids);
    cudaGetSymbolAddress((void**)&p_bsums, d_bsums);

    int nb = (N + 1023) / 1024;
    int mblocks = (N + 127) / 128;

    // 0: weights -> fp16 (196608 elems, 4 per thread)
    cvt_weights<<<192, 256>>>(W_head, W_tail, W_ent, W_rel, W1, W2, p_w16);
    // 1-2: layernorms (fp16 outputs for GEMM inputs)
    ln_kernel<__half><<<(N + 7) / 8, 256>>>(ent, g_ent, b_ent, p_xnh, N);
    ln_kernel<__half><<<(R + 7) / 8, 256>>>(relf, g_rel, b_rel, p_relxh, R);
    // 3: rel projection (fp32 out)
    mm_f16_kernel<0, float><<<dim3(1, 1), 256>>>(
        p_relxh, p_w16 + OFF_WR, nullptr, nullptr, p_relp, R, 128, 128);
    // 4: k projection (fp16 out)
    mm_f16_kernel<0, __half><<<dim3(mblocks, 1), 256>>>(
        p_xnh, p_w16 + OFF_WH, nullptr, nullptr, p_kh, N, 128, 128);
    // 5: q projection (fp32 out)  <- profiled launch
    mm_f16_kernel<0, float><<<dim3(mblocks, 1), 256>>>(
        p_xnh, p_w16 + OFF_WT, nullptr, nullptr, p_q, N, 128, 128);
    // 6: v projection (fp16 out)
    mm_f16_kernel<0, __half><<<dim3(mblocks, 1), 256>>>(
        p_xnh, p_w16 + OFF_WE, nullptr, nullptr, p_vh, N, 128, 128);

    // CSR build
    zero_deg_kernel<<<(N + 255) / 256, 256>>>(p_deg, N);
    hist_kernel<<<(E + 255) / 256, 256>>>(dst, p_deg, E);
    scan1_kernel<<<nb, 1024>>>(p_deg, p_rowoff, p_bsums, N);
    scan2_kernel<<<1, 256>>>(p_bsums, nb);
    scan3_kernel<<<(N + 255) / 256, 256>>>(p_rowoff, p_cursor, p_bsums, N);
    scatter_kernel<<<(E + 255) / 256, 256>>>(src, dst, rid, p_cursor, p_srcs, p_rids, E);

    // attention: raw exp + per-node (1-alpha)/sum
    attn_kernel<<<(N + 7) / 8, 256>>>(p_rowoff, p_deg, p_srcs, p_rids,
                                      p_kh, p_q, p_relp, p_ex, p_nscale, N);

    // PPR hops: v -> A -> B -> A -> (fused last: y fp16, rst fp32)
    hop_kernel<<<(N + 7) / 8, 256>>>(p_rowoff, p_deg, p_srcs, p_ex, p_nscale,
                                     p_vh, p_vh, p_fA, N);
    hop_kernel<<<(N + 7) / 8, 256>>>(p_rowoff, p_deg, p_srcs, p_ex, p_nscale,
                                     p_fA, p_vh, p_fB, N);
    hop_kernel<<<(N + 7) / 8, 256>>>(p_rowoff, p_deg, p_srcs, p_ex, p_nscale,
                                     p_fB, p_vh, p_fA, N);
    hop_last_kernel<<<(N + 7) / 8, 256>>>(p_rowoff, p_deg, p_srcs, p_ex, p_nscale,
                                          p_fA, p_vh, ent, g_ff, b_ff,
                                          p_xnh, p_q, N);   // y -> d_xnh, rst -> d_q

    // FFN: h = relu(y@W1+b1) fp16; out = h@W2 + b2 + rst
    mm_f16_kernel<1, __half><<<dim3(mblocks, 4), 256>>>(
        p_xnh, p_w16 + OFF_W1, b1, nullptr, p_hh, N, 128, 512);
    mm_f16_kernel<2, float><<<dim3(mblocks, 1), 256>>>(
        p_hh, p_w16 + OFF_W2, b2, p_q, out, N, 512, 128);
}

// round 5
// speedup vs baseline: 3.0034x; 1.1257x over previous
#include <cuda_runtime.h>
#include <cuda_fp16.h>
#include <math.h>
#include <stdint.h>

#define D 128
#define H 8
#define NMAX 100000
#define EMAX 1600000
#define RMAX 128
#define ALPHA 0.1f
#define SRCMASK 0xFFFFF

// ---------------- scratch (device globals; no allocations) ----------------
__device__ __half d_xnh[NMAX * D];     // LN(ent) fp16; later y = LN(rst) fp16
__device__ __half d_kqv[NMAX * 384];   // fused k|q|v fp16
__device__ float  d_rst[NMAX * D];     // rst = feat + ent (fp32)
__device__ __half d_fA[NMAX * D];
__device__ __half d_fB[NMAX * D];
__device__ __half d_hh[NMAX * 512];
__device__ __half d_exh[EMAX * H];
__device__ float  d_nscale[NMAX * H];
__device__ __half d_relxh[RMAX * D];
__device__ float  d_relp[RMAX * D];
__device__ __half d_w16[4 * 16384 + 2 * 65536];
__device__ int    d_deg[NMAX];
__device__ int    d_rowoff[NMAX];
__device__ int    d_cursor[NMAX];
__device__ int    d_pk[EMAX];          // src | (rid<<20), CSR order
__device__ int    d_bsums[256];

#define OFF_WKQV 0
#define OFF_WR   49152
#define OFF_W1   65536
#define OFF_W2   131072

// ---------------- typed helpers ----------------
__device__ __forceinline__ float4 ld4(const float* p) { return *(const float4*)p; }
__device__ __forceinline__ float4 ld4(const __half* p) {
    float2 r = *(const float2*)p;
    __half2 h0 = ((const __half2*)&r)[0];
    __half2 h1 = ((const __half2*)&r)[1];
    float2 a = __half22float2(h0), b = __half22float2(h1);
    return make_float4(a.x, a.y, b.x, b.y);
}
__device__ __forceinline__ void st2(float* p, float a, float b) {
    *(float2*)p = make_float2(a, b);
}
__device__ __forceinline__ void st2(__half* p, float a, float b) {
    *(__half2*)p = __floats2half2_rn(a, b);
}
__device__ __forceinline__ uint32_t smem_u32(const void* p) {
    return (uint32_t)__cvta_generic_to_shared(p);
}
__device__ __forceinline__ void cp_async16(uint32_t dst, const void* src, bool pred) {
    int sz = pred ? 16 : 0;
    asm volatile("cp.async.cg.shared.global [%0], [%1], 16, %2;\n"
                 :: "r"(dst), "l"(src), "r"(sz));
}
__device__ __forceinline__ void ldsm4(uint32_t* r, uint32_t addr) {
    asm volatile("ldmatrix.sync.aligned.m8n8.x4.shared.b16 {%0,%1,%2,%3}, [%4];"
                 : "=r"(r[0]), "=r"(r[1]), "=r"(r[2]), "=r"(r[3]) : "r"(addr));
}
__device__ __forceinline__ void ldsm4t(uint32_t* r, uint32_t addr) {
    asm volatile("ldmatrix.sync.aligned.m8n8.x4.trans.shared.b16 {%0,%1,%2,%3}, [%4];"
                 : "=r"(r[0]), "=r"(r[1]), "=r"(r[2]), "=r"(r[3]) : "r"(addr));
}
__device__ __forceinline__ void mma_f16(float* c, const uint32_t* a, const uint32_t* b) {
    asm volatile(
        "mma.sync.aligned.m16n8k16.row.col.f32.f16.f16.f32 "
        "{%0,%1,%2,%3}, {%4,%5,%6,%7}, {%8,%9}, {%0,%1,%2,%3};\n"
        : "+f"(c[0]), "+f"(c[1]), "+f"(c[2]), "+f"(c[3])
        : "r"(a[0]), "r"(a[1]), "r"(a[2]), "r"(a[3]), "r"(b[0]), "r"(b[1]));
}

// ---------------- weight convert: kqv cat + rel + W1 + W2 ----------------
__global__ void cvt_weights(const float* __restrict__ wh, const float* __restrict__ wt,
                            const float* __restrict__ we, const float* __restrict__ wr,
                            const float* __restrict__ w1, const float* __restrict__ w2,
                            __half* __restrict__ out) {
    int base = (blockIdx.x * blockDim.x + threadIdx.x) * 4;
    const float* src; long dst;
    if (base < 16384) {                    // W_head -> cat col 0..127
        int k = base >> 7, c = base & 127;
        src = wh + base; dst = (long)k * 384 + c;
    } else if (base < 32768) {             // W_tail -> cat col 128..255
        int i = base - 16384; int k = i >> 7, c = i & 127;
        src = wt + i; dst = (long)k * 384 + 128 + c;
    } else if (base < 49152) {             // W_ent -> cat col 256..383
        int i = base - 32768; int k = i >> 7, c = i & 127;
        src = we + i; dst = (long)k * 384 + 256 + c;
    } else if (base < 65536) {
        src = wr + (base - 49152); dst = base;
    } else if (base < 131072) {
        src = w1 + (base - 65536); dst = base;
    } else {
        src = w2 + (base - 131072); dst = base;
    }
    float4 v = *(const float4*)src;
    __half2* o = (__half2*)(out + dst);
    o[0] = __floats2half2_rn(v.x, v.y);
    o[1] = __floats2half2_rn(v.z, v.w);
}

// ---------------- CSR build ----------------
__global__ void zero_deg_kernel(int* deg, int n) {
    int i = blockIdx.x * blockDim.x + threadIdx.x;
    if (i < n) deg[i] = 0;
}

__global__ void hist_kernel(const int* __restrict__ dst, int* deg, int E) {
    int e = blockIdx.x * blockDim.x + threadIdx.x;
    if (e < E) atomicAdd(&deg[dst[e]], 1);
}

__global__ void scan1_kernel(const int* __restrict__ deg, int* rowoff, int* bsums, int n) {
    __shared__ int sh[1024];
    int i = blockIdx.x * 1024 + threadIdx.x;
    int v = (i < n) ? deg[i] : 0;
    sh[threadIdx.x] = v;
    __syncthreads();
    for (int off = 1; off < 1024; off <<= 1) {
        int t = (threadIdx.x >= off) ? sh[threadIdx.x - off] : 0;
        __syncthreads();
        sh[threadIdx.x] += t;
        __syncthreads();
    }
    if (i < n) rowoff[i] = sh[threadIdx.x] - v;  // exclusive
    if (threadIdx.x == 1023) bsums[blockIdx.x] = sh[1023];
}

__global__ void scan2_kernel(int* bsums, int nb) {
    __shared__ int sh[256];
    int v = (threadIdx.x < nb) ? bsums[threadIdx.x] : 0;
    sh[threadIdx.x] = v;
    __syncthreads();
    for (int off = 1; off < 256; off <<= 1) {
        int t = (threadIdx.x >= off) ? sh[threadIdx.x - off] : 0;
        __syncthreads();
        sh[threadIdx.x] += t;
        __syncthreads();
    }
    if (threadIdx.x < nb) bsums[threadIdx.x] = sh[threadIdx.x] - v;  // exclusive
}

__global__ void scan3_kernel(int* rowoff, int* cursor, const int* __restrict__ bsums, int n) {
    int i = blockIdx.x * blockDim.x + threadIdx.x;
    if (i < n) {
        int r = rowoff[i] + bsums[i >> 10];
        rowoff[i] = r;
        cursor[i] = r;
    }
}

__global__ void scatter_kernel(const int* __restrict__ src, const int* __restrict__ dst,
                               const int* __restrict__ rid, int* cursor, int* pk, int E) {
    int e = blockIdx.x * blockDim.x + threadIdx.x;
    if (e < E) {
        int p = atomicAdd(&cursor[dst[e]], 1);
        pk[p] = src[e] | (rid[e] << 20);
    }
}

// ---------------- layernorm (warp per row) ----------------
template<typename Tout>
__global__ void ln_kernel(const float* __restrict__ x, const float* __restrict__ g,
                          const float* __restrict__ b, Tout* __restrict__ y, int nrows) {
    int w = (blockIdx.x * blockDim.x + threadIdx.x) >> 5;
    if (w >= nrows) return;
    int lane = threadIdx.x & 31;
    float4 v = *(const float4*)(x + (long)w * D + lane * 4);
    float s = v.x + v.y + v.z + v.w;
    #pragma unroll
    for (int o = 16; o; o >>= 1) s += __shfl_xor_sync(0xffffffffu, s, o);
    float mean = s * (1.0f / 128.0f);
    float dx = v.x - mean, dy = v.y - mean, dz = v.z - mean, dw = v.w - mean;
    float q = dx * dx + dy * dy + dz * dz + dw * dw;
    #pragma unroll
    for (int o = 16; o; o >>= 1) q += __shfl_xor_sync(0xffffffffu, q, o);
    float inv = rsqrtf(q * (1.0f / 128.0f) + 1e-5f);
    float4 g4 = *(const float4*)(g + lane * 4);
    float4 b4 = *(const float4*)(b + lane * 4);
    st2(y + (long)w * D + lane * 4,     dx * inv * g4.x + b4.x, dy * inv * g4.y + b4.y);
    st2(y + (long)w * D + lane * 4 + 2, dz * inv * g4.z + b4.z, dw * inv * g4.w + b4.w);
}

// ---------------- fp16 tensor-core GEMM ----------------
#define AS_STRIDE 40
#define BS_STRIDE 136
template<int EPI, typename Tout>
__global__ void __launch_bounds__(256, 2) mm_f16_kernel(
    const __half* __restrict__ X, const __half* __restrict__ W,
    const float* __restrict__ bias, const float* __restrict__ rst,
    Tout* __restrict__ Y, int M, int K, int Nc)
{
    __shared__ __half As[2][128 * AS_STRIDE];
    __shared__ __half Bs[2][32 * BS_STRIDE];
    const int tid = threadIdx.x;
    const int lane = tid & 31;
    const int warp = tid >> 5;
    const int m_off = (warp & 3) * 32;
    const int n_off = (warp >> 2) * 64;
    const int r0 = blockIdx.x * 128;
    const int n0 = blockIdx.y * 128;

    float acc[2][8][4];
    #pragma unroll
    for (int mi = 0; mi < 2; mi++)
        #pragma unroll
        for (int ni = 0; ni < 8; ni++)
            #pragma unroll
            for (int j = 0; j < 4; j++) acc[mi][ni][j] = 0.0f;

    const int T = K >> 5;

    auto issue = [&](int t, int bf) {
        #pragma unroll
        for (int i = 0; i < 2; i++) {
            int ci = tid + i * 256;
            int row = ci >> 2, kc = (ci & 3) * 8;
            int gr = r0 + row;
            cp_async16(smem_u32(&As[bf][row * AS_STRIDE + kc]),
                       X + (long)gr * K + t * 32 + kc, gr < M);
            int brow = ci >> 4, nc = (ci & 15) * 8;
            cp_async16(smem_u32(&Bs[bf][brow * BS_STRIDE + nc]),
                       W + (long)(t * 32 + brow) * Nc + n0 + nc, true);
        }
        asm volatile("cp.async.commit_group;\n" ::);
    };

    issue(0, 0);
    for (int t = 0; t < T; t++) {
        if (t + 1 < T) {
            issue(t + 1, (t + 1) & 1);
            asm volatile("cp.async.wait_group 1;\n" ::);
        } else {
            asm volatile("cp.async.wait_group 0;\n" ::);
        }
        __syncthreads();
        const __half* A = As[t & 1];
        const __half* B = Bs[t & 1];
        #pragma unroll
        for (int ks = 0; ks < 2; ks++) {
            uint32_t a[2][4];
            #pragma unroll
            for (int mi = 0; mi < 2; mi++) {
                int m = m_off + mi * 16 + (lane & 7) + (lane & 8);
                int k = ks * 16 + ((lane >> 4) << 3);
                ldsm4(a[mi], smem_u32(&A[m * AS_STRIDE + k]));
            }
            uint32_t b[8][2];
            #pragma unroll
            for (int nb = 0; nb < 4; nb++) {
                uint32_t r[4];
                int k = ks * 16 + (lane & 7) + (lane & 8);
                int n = n_off + nb * 16 + ((lane >> 4) << 3);
                ldsm4t(r, smem_u32(&B[k * BS_STRIDE + n]));
                b[nb * 2][0] = r[0]; b[nb * 2][1] = r[1];
                b[nb * 2 + 1][0] = r[2]; b[nb * 2 + 1][1] = r[3];
            }
            #pragma unroll
            for (int mi = 0; mi < 2; mi++)
                #pragma unroll
                for (int ni = 0; ni < 8; ni++)
                    mma_f16(acc[mi][ni], a[mi], b[ni]);
        }
        __syncthreads();
    }

    #pragma unroll
    for (int mi = 0; mi < 2; mi++) {
        #pragma unroll
        for (int half = 0; half < 2; half++) {
            int row = m_off + mi * 16 + (lane >> 2) + half * 8;
            int gr = r0 + row;
            if (gr >= M) continue;
            #pragma unroll
            for (int ni = 0; ni < 8; ni++) {
                int col = n_off + ni * 8 + (lane & 3) * 2;
                float v0 = acc[mi][ni][half * 2 + 0];
                float v1 = acc[mi][ni][half * 2 + 1];
                if (EPI == 1) {
                    v0 = fmaxf(v0 + bias[n0 + col], 0.0f);
                    v1 = fmaxf(v1 + bias[n0 + col + 1], 0.0f);
                } else if (EPI == 2) {
                    v0 += bias[n0 + col] + rst[(long)gr * Nc + n0 + col];
                    v1 += bias[n0 + col + 1] + rst[(long)gr * Nc + n0 + col + 1];
                }
                st2(Y + (long)gr * Nc + n0 + col, v0, v1);
            }
        }
    }
}

// ---------------- attention (warp per dst node) ----------------
__global__ void attn_kernel(const int* __restrict__ rowoff, const int* __restrict__ deg,
                            const int* __restrict__ pk,
                            const __half* __restrict__ kqv,
                            const float* __restrict__ relp, __half* __restrict__ exh,
                            float* __restrict__ nscale, int N) {
    int w = (blockIdx.x * blockDim.x + threadIdx.x) >> 5;
    if (w >= N) return;
    int lane = threadIdx.x & 31;
    int head4 = lane >> 2;
    int start = rowoff[w];
    int dg = deg[w];
    float4 q4 = ld4(kqv + (long)w * 384 + 128 + lane * 4);
    float c = log1pf((float)dg) * 0.25f;  // log_in / sqrt(DH)
    float sum = 0.0f;
    int i = 0;
    for (; i + 2 <= dg; i += 2) {
        int pk0 = pk[start + i], pk1 = pk[start + i + 1];
        float4 k0 = ld4(kqv + (long)(pk0 & SRCMASK) * 384 + lane * 4);
        float4 k1 = ld4(kqv + (long)(pk1 & SRCMASK) * 384 + lane * 4);
        float4 r0 = ld4(relp + (long)(pk0 >> 20) * D + lane * 4);
        float4 r1 = ld4(relp + (long)(pk1 >> 20) * D + lane * 4);
        float p0 = k0.x * r0.x * q4.x + k0.y * r0.y * q4.y + k0.z * r0.z * q4.z + k0.w * r0.w * q4.w;
        float p1 = k1.x * r1.x * q4.x + k1.y * r1.y * q4.y + k1.z * r1.z * q4.z + k1.w * r1.w * q4.w;
        p0 += __shfl_xor_sync(0xffffffffu, p0, 1);
        p1 += __shfl_xor_sync(0xffffffffu, p1, 1);
        p0 += __shfl_xor_sync(0xffffffffu, p0, 2);
        p1 += __shfl_xor_sync(0xffffffffu, p1, 2);
        float e0 = __expf(p0 * c);   // logits tiny: no max-subtraction needed
        float e1 = __expf(p1 * c);
        if ((lane & 3) == 0) {
            exh[(long)(start + i) * H + head4] = __float2half(e0);
            exh[(long)(start + i + 1) * H + head4] = __float2half(e1);
        }
        sum += e0 + e1;
    }
    if (i < dg) {
        int pk0 = pk[start + i];
        float4 k0 = ld4(kqv + (long)(pk0 & SRCMASK) * 384 + lane * 4);
        float4 r0 = ld4(relp + (long)(pk0 >> 20) * D + lane * 4);
        float p0 = k0.x * r0.x * q4.x + k0.y * r0.y * q4.y + k0.z * r0.z * q4.z + k0.w * r0.w * q4.w;
        p0 += __shfl_xor_sync(0xffffffffu, p0, 1);
        p0 += __shfl_xor_sync(0xffffffffu, p0, 2);
        float e0 = __expf(p0 * c);
        if ((lane & 3) == 0) exh[(long)(start + i) * H + head4] = __float2half(e0);
        sum += e0;
    }
    float s_h = __shfl_sync(0xffffffffu, sum, (lane & 7) * 4);
    if (lane < 8)
        nscale[(long)w * H + lane] = (s_h > 0.0f) ? ((1.0f - ALPHA) / s_h) : 0.0f;
}

// ---------------- PPR diffusion hop (warp per dst node, unroll-2) ----------------
__global__ void hop_kernel(const int* __restrict__ rowoff, const int* __restrict__ deg,
                           const int* __restrict__ pk, const __half* __restrict__ exh,
                           const float* __restrict__ nscale,
                           const __half* __restrict__ fin, int instride,
                           const __half* __restrict__ f0, int f0stride,
                           __half* __restrict__ fout, int N) {
    int w = (blockIdx.x * blockDim.x + threadIdx.x) >> 5;
    if (w >= N) return;
    int lane = threadIdx.x & 31;
    int head = lane >> 2;
    int start = rowoff[w];
    int dg = deg[w];
    float4 acc = make_float4(0.f, 0.f, 0.f, 0.f);
    int i = 0;
    for (; i + 2 <= dg; i += 2) {
        int pk0 = pk[start + i], pk1 = pk[start + i + 1];
        float e0 = __half2float(exh[(long)(start + i) * H + head]);
        float e1 = __half2float(exh[(long)(start + i + 1) * H + head]);
        float4 fa = ld4(fin + (long)(pk0 & SRCMASK) * instride + lane * 4);
        float4 fb = ld4(fin + (long)(pk1 & SRCMASK) * instride + lane * 4);
        acc.x += e0 * fa.x + e1 * fb.x;
        acc.y += e0 * fa.y + e1 * fb.y;
        acc.z += e0 * fa.z + e1 * fb.z;
        acc.w += e0 * fa.w + e1 * fb.w;
    }
    if (i < dg) {
        int pk0 = pk[start + i];
        float e0 = __half2float(exh[(long)(start + i) * H + head]);
        float4 fa = ld4(fin + (long)(pk0 & SRCMASK) * instride + lane * 4);
        acc.x += e0 * fa.x;
        acc.y += e0 * fa.y;
        acc.z += e0 * fa.z;
        acc.w += e0 * fa.w;
    }
    float sc = nscale[(long)w * H + head];
    float4 z = ld4(f0 + (long)w * f0stride + lane * 4);
    acc.x = acc.x * sc + ALPHA * z.x;
    acc.y = acc.y * sc + ALPHA * z.y;
    acc.z = acc.z * sc + ALPHA * z.z;
    acc.w = acc.w * sc + ALPHA * z.w;
    float2 pkd;
    ((__half2*)&pkd)[0] = __floats2half2_rn(acc.x, acc.y);
    ((__half2*)&pkd)[1] = __floats2half2_rn(acc.z, acc.w);
    *(float2*)(fout + (long)w * D + lane * 4) = pkd;
}

// ---------------- last hop fused with residual + LN ----------------
__global__ void hop_last_kernel(const int* __restrict__ rowoff, const int* __restrict__ deg,
                                const int* __restrict__ pk, const __half* __restrict__ exh,
                                const float* __restrict__ nscale,
                                const __half* __restrict__ fin, const __half* __restrict__ f0,
                                const float* __restrict__ ent,
                                const float* __restrict__ g, const float* __restrict__ b,
                                __half* __restrict__ y, float* __restrict__ rst, int N) {
    int w = (blockIdx.x * blockDim.x + threadIdx.x) >> 5;
    if (w >= N) return;
    int lane = threadIdx.x & 31;
    int head = lane >> 2;
    int start = rowoff[w];
    int dg = deg[w];
    float4 acc = make_float4(0.f, 0.f, 0.f, 0.f);
    int i = 0;
    for (; i + 2 <= dg; i += 2) {
        int pk0 = pk[start + i], pk1 = pk[start + i + 1];
        float e0 = __half2float(exh[(long)(start + i) * H + head]);
        float e1 = __half2float(exh[(long)(start + i + 1) * H + head]);
        float4 fa = ld4(fin + (long)(pk0 & SRCMASK) * D + lane * 4);
        float4 fb = ld4(fin + (long)(pk1 & SRCMASK) * D + lane * 4);
        acc.x += e0 * fa.x + e1 * fb.x;
        acc.y += e0 * fa.y + e1 * fb.y;
        acc.z += e0 * fa.z + e1 * fb.z;
        acc.w += e0 * fa.w + e1 * fb.w;
    }
    if (i < dg) {
        int pk0 = pk[start + i];
        float e0 = __half2float(exh[(long)(start + i) * H + head]);
        float4 fa = ld4(fin + (long)(pk0 & SRCMASK) * D + lane * 4);
        acc.x += e0 * fa.x;
        acc.y += e0 * fa.y;
        acc.z += e0 * fa.z;
        acc.w += e0 * fa.w;
    }
    float sc = nscale[(long)w * H + head];
    float4 z = ld4(f0 + (long)w * 384 + lane * 4);
    float4 e4 = *(const float4*)(ent + (long)w * D + lane * 4);
    float4 v;
    v.x = acc.x * sc + ALPHA * z.x + e4.x;
    v.y = acc.y * sc + ALPHA * z.y + e4.y;
    v.z = acc.z * sc + ALPHA * z.z + e4.z;
    v.w = acc.w * sc + ALPHA * z.w + e4.w;
    *(float4*)(rst + (long)w * D + lane * 4) = v;
    float s = v.x + v.y + v.z + v.w;
    #pragma unroll
    for (int o = 16; o; o >>= 1) s += __shfl_xor_sync(0xffffffffu, s, o);
    float mean = s * (1.0f / 128.0f);
    float dx = v.x - mean, dy = v.y - mean, dz = v.z - mean, dw = v.w - mean;
    float q = dx * dx + dy * dy + dz * dz + dw * dw;
    #pragma unroll
    for (int o = 16; o; o >>= 1) q += __shfl_xor_sync(0xffffffffu, q, o);
    float inv = rsqrtf(q * (1.0f / 128.0f) + 1e-5f);
    float4 g4 = *(const float4*)(g + lane * 4);
    float4 b4 = *(const float4*)(b + lane * 4);
    st2(y + (long)w * D + lane * 4,     dx * inv * g4.x + b4.x, dy * inv * g4.y + b4.y);
    st2(y + (long)w * D + lane * 4 + 2, dz * inv * g4.z + b4.z, dw * inv * g4.w + b4.w);
}

// ---------------- launch ----------------
extern "C" void kernel_launch(void* const* d_in, const int* in_sizes, int n_in,
                              void* d_out, int out_size) {
    const float* ent    = (const float*)d_in[0];
    const float* relf   = (const float*)d_in[1];
    const float* W_head = (const float*)d_in[2];
    const float* W_tail = (const float*)d_in[3];
    const float* W_ent  = (const float*)d_in[4];
    const float* W_rel  = (const float*)d_in[5];
    const float* g_ent  = (const float*)d_in[6];
    const float* b_ent  = (const float*)d_in[7];
    const float* g_rel  = (const float*)d_in[8];
    const float* b_rel  = (const float*)d_in[9];
    const float* g_ff   = (const float*)d_in[10];
    const float* b_ff   = (const float*)d_in[11];
    const float* W1     = (const float*)d_in[12];
    const float* b1     = (const float*)d_in[13];
    const float* W2     = (const float*)d_in[14];
    const float* b2     = (const float*)d_in[15];
    const int*   src    = (const int*)d_in[16];
    const int*   dst    = (const int*)d_in[17];
    const int*   rid    = (const int*)d_in[18];
    float* out = (float*)d_out;

    int N = in_sizes[0] / D;
    int R = in_sizes[1] / D;
    int E = in_sizes[16];

    float *p_rst, *p_nscale, *p_relp;
    __half *p_xnh, *p_kqv, *p_fA, *p_fB, *p_hh, *p_exh, *p_relxh, *p_w16;
    int *p_deg, *p_rowoff, *p_cursor, *p_pk, *p_bsums;
    cudaGetSymbolAddress((void**)&p_xnh, d_xnh);
    cudaGetSymbolAddress((void**)&p_kqv, d_kqv);
    cudaGetSymbolAddress((void**)&p_rst, d_rst);
    cudaGetSymbolAddress((void**)&p_fA, d_fA);
    cudaGetSymbolAddress((void**)&p_fB, d_fB);
    cudaGetSymbolAddress((void**)&p_hh, d_hh);
    cudaGetSymbolAddress((void**)&p_exh, d_exh);
    cudaGetSymbolAddress((void**)&p_nscale, d_nscale);
    cudaGetSymbolAddress((void**)&p_relxh, d_relxh);
    cudaGetSymbolAddress((void**)&p_relp, d_relp);
    cudaGetSymbolAddress((void**)&p_w16, d_w16);
    cudaGetSymbolAddress((void**)&p_deg, d_deg);
    cudaGetSymbolAddress((void**)&p_rowoff, d_rowoff);
    cudaGetSymbolAddress((void**)&p_cursor, d_cursor);
    cudaGetSymbolAddress((void**)&p_pk, d_pk);
    cudaGetSymbolAddress((void**)&p_bsums, d_bsums);

    int nb = (N + 1023) / 1024;
    int mblocks = (N + 127) / 128;

    // ordered so launch idx 5 (ncu -s 5 -c 1) is the big fused kqv GEMM
    cvt_weights<<<192, 256>>>(W_head, W_tail, W_ent, W_rel, W1, W2, p_w16);   // 0
    ln_kernel<__half><<<(N + 7) / 8, 256>>>(ent, g_ent, b_ent, p_xnh, N);     // 1
    zero_deg_kernel<<<(N + 255) / 256, 256>>>(p_deg, N);                      // 2
    hist_kernel<<<(E + 255) / 256, 256>>>(dst, p_deg, E);                     // 3
    scan1_kernel<<<nb, 1024>>>(p_deg, p_rowoff, p_bsums, N);                  // 4
    mm_f16_kernel<0, __half><<<dim3(mblocks, 3), 256>>>(                      // 5 <- profiled
        p_xnh, p_w16 + OFF_WKQV, nullptr, nullptr, p_kqv, N, 128, 384);
    scan2_kernel<<<1, 256>>>(p_bsums, nb);
    scan3_kernel<<<(N + 255) / 256, 256>>>(p_rowoff, p_cursor, p_bsums, N);
    scatter_kernel<<<(E + 255) / 256, 256>>>(src, dst, rid, p_cursor, p_pk, E);
    ln_kernel<__half><<<(R + 7) / 8, 256>>>(relf, g_rel, b_rel, p_relxh, R);
    mm_f16_kernel<0, float><<<dim3(1, 1), 256>>>(
        p_relxh, p_w16 + OFF_WR, nullptr, nullptr, p_relp, R, 128, 128);

    // attention: raw exp (fp16) + per-node (1-alpha)/sum
    attn_kernel<<<(N + 7) / 8, 256>>>(p_rowoff, p_deg, p_pk, p_kqv,
                                      p_relp, p_exh, p_nscale, N);

    // PPR hops: v(in kqv) -> A -> B -> A -> (fused last: y fp16, rst fp32)
    hop_kernel<<<(N + 7) / 8, 256>>>(p_rowoff, p_deg, p_pk, p_exh, p_nscale,
                                     p_kqv + 256, 384, p_kqv + 256, 384, p_fA, N);
    hop_kernel<<<(N + 7) / 8, 256>>>(p_rowoff, p_deg, p_pk, p_exh, p_nscale,
                                     p_fA, 128, p_kqv + 256, 384, p_fB, N);
    hop_kernel<<<(N + 7) / 8, 256>>>(p_rowoff, p_deg, p_pk, p_exh, p_nscale,
                                     p_fB, 128, p_kqv + 256, 384, p_fA, N);
    hop_last_kernel<<<(N + 7) / 8, 256>>>(p_rowoff, p_deg, p_pk, p_exh, p_nscale,
                                          p_fA, p_kqv + 256, ent, g_ff, b_ff,
                                          p_xnh, p_rst, N);   // y -> d_xnh

    // FFN: h = relu(y@W1+b1) fp16; out = h@W2 + b2 + rst
    mm_f16_kernel<1, __half><<<dim3(mblocks, 4), 256>>>(
        p_xnh, p_w16 + OFF_W1, b1, nullptr, p_hh, N, 128, 512);
    mm_f16_kernel<2, float><<<dim3(mblocks, 1), 256>>>(
        p_hh, p_w16 + OFF_W2, b2, p_rst, out, N, 512, 128);
}

// round 7
// speedup vs baseline: 3.3203x; 1.1055x over previous
#include <cuda_runtime.h>
#include <cuda_fp16.h>
#include <math.h>
#include <stdint.h>

#define D 128
#define H 8
#define NMAX 100000
#define EMAX 1600000
#define RMAX 128
#define ALPHA 0.1f
#define SRCMASK 0xFFFFF

// ---------------- scratch (device globals; no allocations) ----------------
__device__ __half d_xnh[NMAX * D];     // LN(ent) fp16; later y = LN(rst) fp16
__device__ __half d_kqv[NMAX * 384];   // fused k|q|v fp16
__device__ float  d_rst[NMAX * D];     // rst = feat + ent (fp32)
__device__ __half d_fA[NMAX * D];
__device__ __half d_fB[NMAX * D];
__device__ __half d_exh[EMAX * H];
__device__ float  d_nscale[NMAX * H];
__device__ __half d_relxh[RMAX * D];
__device__ float  d_relp[RMAX * D];
__device__ __half d_w16[4 * 16384 + 2 * 65536];
__device__ int    d_deg[NMAX];
__device__ int    d_rowoff[NMAX];
__device__ int    d_cursor[NMAX];
__device__ int    d_pk[EMAX];          // src | (rid<<20), CSR order
__device__ int    d_bsums[256];

#define OFF_WKQV 0
#define OFF_WR   49152
#define OFF_W1   65536
#define OFF_W2   131072

// ---------------- typed helpers ----------------
__device__ __forceinline__ float4 ld4(const float* p) { return *(const float4*)p; }
__device__ __forceinline__ float4 ld4(const __half* p) {
    float2 r = *(const float2*)p;
    __half2 h0 = ((const __half2*)&r)[0];
    __half2 h1 = ((const __half2*)&r)[1];
    float2 a = __half22float2(h0), b = __half22float2(h1);
    return make_float4(a.x, a.y, b.x, b.y);
}
__device__ __forceinline__ void st2(float* p, float a, float b) {
    *(float2*)p = make_float2(a, b);
}
__device__ __forceinline__ void st2(__half* p, float a, float b) {
    *(__half2*)p = __floats2half2_rn(a, b);
}
__device__ __forceinline__ uint32_t smem_u32(const void* p) {
    return (uint32_t)__cvta_generic_to_shared(p);
}
__device__ __forceinline__ void cp_async16(uint32_t dst, const void* src, bool pred) {
    int sz = pred ? 16 : 0;
    asm volatile("cp.async.cg.shared.global [%0], [%1], 16, %2;\n"
                 :: "r"(dst), "l"(src), "r"(sz));
}
__device__ __forceinline__ void ldsm4(uint32_t* r, uint32_t addr) {
    asm volatile("ldmatrix.sync.aligned.m8n8.x4.shared.b16 {%0,%1,%2,%3}, [%4];"
                 : "=r"(r[0]), "=r"(r[1]), "=r"(r[2]), "=r"(r[3]) : "r"(addr));
}
__device__ __forceinline__ void ldsm4t(uint32_t* r, uint32_t addr) {
    asm volatile("ldmatrix.sync.aligned.m8n8.x4.trans.shared.b16 {%0,%1,%2,%3}, [%4];"
                 : "=r"(r[0]), "=r"(r[1]), "=r"(r[2]), "=r"(r[3]) : "r"(addr));
}
__device__ __forceinline__ void mma_f16(float* c, const uint32_t* a, const uint32_t* b) {
    asm volatile(
        "mma.sync.aligned.m16n8k16.row.col.f32.f16.f16.f32 "
        "{%0,%1,%2,%3}, {%4,%5,%6,%7}, {%8,%9}, {%0,%1,%2,%3};\n"
        : "+f"(c[0]), "+f"(c[1]), "+f"(c[2]), "+f"(c[3])
        : "r"(a[0]), "r"(a[1]), "r"(a[2]), "r"(a[3]), "r"(b[0]), "r"(b[1]));
}

// ---------------- weight convert: kqv cat + rel + W1 + W2 ----------------
__global__ void cvt_weights(const float* __restrict__ wh, const float* __restrict__ wt,
                            const float* __restrict__ we, const float* __restrict__ wr,
                            const float* __restrict__ w1, const float* __restrict__ w2,
                            __half* __restrict__ out) {
    int base = (blockIdx.x * blockDim.x + threadIdx.x) * 4;
    const float* src; long dst;
    if (base < 16384) {                    // W_head -> cat col 0..127
        int k = base >> 7, c = base & 127;
        src = wh + base; dst = (long)k * 384 + c;
    } else if (base < 32768) {             // W_tail -> cat col 128..255
        int i = base - 16384; int k = i >> 7, c = i & 127;
        src = wt + i; dst = (long)k * 384 + 128 + c;
    } else if (base < 49152) {             // W_ent -> cat col 256..383
        int i = base - 32768; int k = i >> 7, c = i & 127;
        src = we + i; dst = (long)k * 384 + 256 + c;
    } else if (base < 65536) {
        src = wr + (base - 49152); dst = base;
    } else if (base < 131072) {
        src = w1 + (base - 65536); dst = base;
    } else {
        src = w2 + (base - 131072); dst = base;
    }
    float4 v = *(const float4*)src;
    __half2* o = (__half2*)(out + dst);
    o[0] = __floats2half2_rn(v.x, v.y);
    o[1] = __floats2half2_rn(v.z, v.w);
}

// ---------------- CSR build ----------------
__global__ void zero_deg_kernel(int* deg, int n) {
    int i = blockIdx.x * blockDim.x + threadIdx.x;
    if (i < n) deg[i] = 0;
}

__global__ void hist_kernel(const int* __restrict__ dst, int* deg, int E) {
    int e = blockIdx.x * blockDim.x + threadIdx.x;
    if (e < E) atomicAdd(&deg[dst[e]], 1);
}

__global__ void scan1_kernel(const int* __restrict__ deg, int* rowoff, int* bsums, int n) {
    __shared__ int sh[1024];
    int i = blockIdx.x * 1024 + threadIdx.x;
    int v = (i < n) ? deg[i] : 0;
    sh[threadIdx.x] = v;
    __syncthreads();
    for (int off = 1; off < 1024; off <<= 1) {
        int t = (threadIdx.x >= off) ? sh[threadIdx.x - off] : 0;
        __syncthreads();
        sh[threadIdx.x] += t;
        __syncthreads();
    }
    if (i < n) rowoff[i] = sh[threadIdx.x] - v;  // exclusive
    if (threadIdx.x == 1023) bsums[blockIdx.x] = sh[1023];
}

__global__ void scan2_kernel(int* bsums, int nb) {
    __shared__ int sh[256];
    int v = (threadIdx.x < nb) ? bsums[threadIdx.x] : 0;
    sh[threadIdx.x] = v;
    __syncthreads();
    for (int off = 1; off < 256; off <<= 1) {
        int t = (threadIdx.x >= off) ? sh[threadIdx.x - off] : 0;
        __syncthreads();
        sh[threadIdx.x] += t;
        __syncthreads();
    }
    if (threadIdx.x < nb) bsums[threadIdx.x] = sh[threadIdx.x] - v;  // exclusive
}

__global__ void scan3_kernel(int* rowoff, int* cursor, const int* __restrict__ bsums, int n) {
    int i = blockIdx.x * blockDim.x + threadIdx.x;
    if (i < n) {
        int r = rowoff[i] + bsums[i >> 10];
        rowoff[i] = r;
        cursor[i] = r;
    }
}

__global__ void scatter_kernel(const int* __restrict__ src, const int* __restrict__ dst,
                               const int* __restrict__ rid, int* cursor, int* pk, int E) {
    int e = blockIdx.x * blockDim.x + threadIdx.x;
    if (e < E) {
        int p = atomicAdd(&cursor[dst[e]], 1);
        pk[p] = src[e] | (rid[e] << 20);
    }
}

// ---------------- layernorm (warp per row) ----------------
template<typename Tout>
__global__ void ln_kernel(const float* __restrict__ x, const float* __restrict__ g,
                          const float* __restrict__ b, Tout* __restrict__ y, int nrows) {
    int w = (blockIdx.x * blockDim.x + threadIdx.x) >> 5;
    if (w >= nrows) return;
    int lane = threadIdx.x & 31;
    float4 v = *(const float4*)(x + (long)w * D + lane * 4);
    float s = v.x + v.y + v.z + v.w;
    #pragma unroll
    for (int o = 16; o; o >>= 1) s += __shfl_xor_sync(0xffffffffu, s, o);
    float mean = s * (1.0f / 128.0f);
    float dx = v.x - mean, dy = v.y - mean, dz = v.z - mean, dw = v.w - mean;
    float q = dx * dx + dy * dy + dz * dz + dw * dw;
    #pragma unroll
    for (int o = 16; o; o >>= 1) q += __shfl_xor_sync(0xffffffffu, q, o);
    float inv = rsqrtf(q * (1.0f / 128.0f) + 1e-5f);
    float4 g4 = *(const float4*)(g + lane * 4);
    float4 b4 = *(const float4*)(b + lane * 4);
    st2(y + (long)w * D + lane * 4,     dx * inv * g4.x + b4.x, dy * inv * g4.y + b4.y);
    st2(y + (long)w * D + lane * 4 + 2, dz * inv * g4.z + b4.z, dw * inv * g4.w + b4.w);
}

// ---------------- fp16 tensor-core GEMM (projections) ----------------
#define AS_STRIDE 40
#define BS_STRIDE 136
template<int EPI, typename Tout>
__global__ void __launch_bounds__(256, 2) mm_f16_kernel(
    const __half* __restrict__ X, const __half* __restrict__ W,
    const float* __restrict__ bias, const float* __restrict__ rst,
    Tout* __restrict__ Y, int M, int K, int Nc)
{
    __shared__ __half As[2][128 * AS_STRIDE];
    __shared__ __half Bs[2][32 * BS_STRIDE];
    const int tid = threadIdx.x;
    const int lane = tid & 31;
    const int warp = tid >> 5;
    const int m_off = (warp & 3) * 32;
    const int n_off = (warp >> 2) * 64;
    const int r0 = blockIdx.x * 128;
    const int n0 = blockIdx.y * 128;

    float acc[2][8][4];
    #pragma unroll
    for (int mi = 0; mi < 2; mi++)
        #pragma unroll
        for (int ni = 0; ni < 8; ni++)
            #pragma unroll
            for (int j = 0; j < 4; j++) acc[mi][ni][j] = 0.0f;

    const int T = K >> 5;

    auto issue = [&](int t, int bf) {
        #pragma unroll
        for (int i = 0; i < 2; i++) {
            int ci = tid + i * 256;
            int row = ci >> 2, kc = (ci & 3) * 8;
            int gr = r0 + row;
            cp_async16(smem_u32(&As[bf][row * AS_STRIDE + kc]),
                       X + (long)gr * K + t * 32 + kc, gr < M);
            int brow = ci >> 4, nc = (ci & 15) * 8;
            cp_async16(smem_u32(&Bs[bf][brow * BS_STRIDE + nc]),
                       W + (long)(t * 32 + brow) * Nc + n0 + nc, true);
        }
        asm volatile("cp.async.commit_group;\n" ::);
    };

    issue(0, 0);
    for (int t = 0; t < T; t++) {
        if (t + 1 < T) {
            issue(t + 1, (t + 1) & 1);
            asm volatile("cp.async.wait_group 1;\n" ::);
        } else {
            asm volatile("cp.async.wait_group 0;\n" ::);
        }
        __syncthreads();
        const __half* A = As[t & 1];
        const __half* B = Bs[t & 1];
        #pragma unroll
        for (int ks = 0; ks < 2; ks++) {
            uint32_t a[2][4];
            #pragma unroll
            for (int mi = 0; mi < 2; mi++) {
                int m = m_off + mi * 16 + (lane & 7) + (lane & 8);
                int k = ks * 16 + ((lane >> 4) << 3);
                ldsm4(a[mi], smem_u32(&A[m * AS_STRIDE + k]));
            }
            uint32_t b[8][2];
            #pragma unroll
            for (int nb = 0; nb < 4; nb++) {
                uint32_t r[4];
                int k = ks * 16 + (lane & 7) + (lane & 8);
                int n = n_off + nb * 16 + ((lane >> 4) << 3);
                ldsm4t(r, smem_u32(&B[k * BS_STRIDE + n]));
                b[nb * 2][0] = r[0]; b[nb * 2][1] = r[1];
                b[nb * 2 + 1][0] = r[2]; b[nb * 2 + 1][1] = r[3];
            }
            #pragma unroll
            for (int mi = 0; mi < 2; mi++)
                #pragma unroll
                for (int ni = 0; ni < 8; ni++)
                    mma_f16(acc[mi][ni], a[mi], b[ni]);
        }
        __syncthreads();
    }

    #pragma unroll
    for (int mi = 0; mi < 2; mi++) {
        #pragma unroll
        for (int half = 0; half < 2; half++) {
            int row = m_off + mi * 16 + (lane >> 2) + half * 8;
            int gr = r0 + row;
            if (gr >= M) continue;
            #pragma unroll
            for (int ni = 0; ni < 8; ni++) {
                int col = n_off + ni * 8 + (lane & 3) * 2;
                float v0 = acc[mi][ni][half * 2 + 0];
                float v1 = acc[mi][ni][half * 2 + 1];
                st2(Y + (long)gr * Nc + n0 + col, v0, v1);
            }
        }
    }
}

// ---------------- fused FFN: out = relu(y@W1+b1)@W2 + b2 + rst ----------------
// K-split over the 512 hidden dim into 4 chunks of 128; h stays in smem.
// All four 128x128 smem tiles use stride FS_STRIDE (full-width rows).
#define FS_STRIDE 136
#define FFN_SMEM (4 * 128 * FS_STRIDE * 2)
__global__ void __launch_bounds__(256) ffn_fused_kernel(
    const __half* __restrict__ Yh, const __half* __restrict__ W1,
    const __half* __restrict__ W2, const float* __restrict__ b1,
    const float* __restrict__ b2, const float* __restrict__ rst,
    float* __restrict__ out, int M)
{
    extern __shared__ __half fsm[];
    __half* As  = fsm;                                     // 128 x 136
    __half* Hs  = fsm + 128 * FS_STRIDE;                   // 128 x 136
    __half* Bs0 = fsm + 2 * 128 * FS_STRIDE;               // 128 x 136
    __half* Bs1 = Bs0 + 128 * FS_STRIDE;                   // 128 x 136
    const int tid = threadIdx.x;
    const int lane = tid & 31;
    const int warp = tid >> 5;
    const int m_off = (warp & 3) * 32;
    const int n_off = (warp >> 2) * 64;
    const int r0 = blockIdx.x * 128;

    auto load_w = [&](const __half* Wsrc, int row0, int col0, int ldw, __half* dstBs) {
        #pragma unroll
        for (int i = 0; i < 8; i++) {
            int ci = tid + i * 256;
            int r = ci >> 4, nc = (ci & 15) * 8;
            cp_async16(smem_u32(&dstBs[r * FS_STRIDE + nc]),
                       Wsrc + (long)(row0 + r) * ldw + col0 + nc, true);
        }
    };

    // prologue: Y tile + W1 chunk 0
    #pragma unroll
    for (int i = 0; i < 8; i++) {
        int ci = tid + i * 256;
        int r = ci >> 4, kc = (ci & 15) * 8;
        int gr = r0 + r;
        cp_async16(smem_u32(&As[r * FS_STRIDE + kc]), Yh + (long)gr * D + kc, gr < M);
    }
    load_w(W1, 0, 0, 512, Bs0);
    asm volatile("cp.async.commit_group;\n" ::);

    float acc2[2][8][4];
    #pragma unroll
    for (int mi = 0; mi < 2; mi++)
        #pragma unroll
        for (int ni = 0; ni < 8; ni++)
            #pragma unroll
            for (int j = 0; j < 4; j++) acc2[mi][ni][j] = 0.0f;

    // full 128x128x128 GEMM from smem A x B, both stride FS_STRIDE
    auto gemm128 = [&](const __half* A, const __half* B, float acc[2][8][4]) {
        #pragma unroll
        for (int ks = 0; ks < 8; ks++) {
            uint32_t a[2][4];
            #pragma unroll
            for (int mi = 0; mi < 2; mi++) {
                int m = m_off + mi * 16 + (lane & 7) + (lane & 8);
                int k = ks * 16 + ((lane >> 4) << 3);
                ldsm4(a[mi], smem_u32(&A[m * FS_STRIDE + k]));
            }
            uint32_t b[8][2];
            #pragma unroll
            for (int nb = 0; nb < 4; nb++) {
                uint32_t r[4];
                int k = ks * 16 + (lane & 7) + (lane & 8);
                int n = n_off + nb * 16 + ((lane >> 4) << 3);
                ldsm4t(r, smem_u32(&B[k * FS_STRIDE + n]));
                b[nb * 2][0] = r[0]; b[nb * 2][1] = r[1];
                b[nb * 2 + 1][0] = r[2]; b[nb * 2 + 1][1] = r[3];
            }
            #pragma unroll
            for (int mi = 0; mi < 2; mi++)
                #pragma unroll
                for (int ni = 0; ni < 8; ni++)
                    mma_f16(acc[mi][ni], a[mi], b[ni]);
        }
    };

    for (int c = 0; c < 4; c++) {
        // prefetch W2 chunk c
        load_w(W2, c * 128, 0, 128, Bs1);
        asm volatile("cp.async.commit_group;\n" ::);
        // wait for W1 chunk c (and As on c==0)
        asm volatile("cp.async.wait_group 1;\n" ::);
        __syncthreads();

        // GEMM1: h_c = relu(As @ W1c + b1c)
        float accT[2][8][4];
        #pragma unroll
        for (int mi = 0; mi < 2; mi++)
            #pragma unroll
            for (int ni = 0; ni < 8; ni++)
                #pragma unroll
                for (int j = 0; j < 4; j++) accT[mi][ni][j] = 0.0f;
        gemm128(As, Bs0, accT);
        __syncthreads();   // all Bs0 reads done before overwrite

        if (c < 3) {
            load_w(W1, 0, (c + 1) * 128, 512, Bs0);
            asm volatile("cp.async.commit_group;\n" ::);
        }

        // epilogue: bias + relu -> Hs (fp16)
        #pragma unroll
        for (int mi = 0; mi < 2; mi++) {
            #pragma unroll
            for (int half = 0; half < 2; half++) {
                int row = m_off + mi * 16 + (lane >> 2) + half * 8;
                #pragma unroll
                for (int ni = 0; ni < 8; ni++) {
                    int col = n_off + ni * 8 + (lane & 3) * 2;
                    float v0 = fmaxf(accT[mi][ni][half * 2 + 0] + b1[c * 128 + col], 0.0f);
                    float v1 = fmaxf(accT[mi][ni][half * 2 + 1] + b1[c * 128 + col + 1], 0.0f);
                    *(__half2*)(&Hs[row * FS_STRIDE + col]) = __floats2half2_rn(v0, v1);
                }
            }
        }
        // wait for W2 chunk c
        if (c < 3) { asm volatile("cp.async.wait_group 1;\n" ::); }
        else       { asm volatile("cp.async.wait_group 0;\n" ::); }
        __syncthreads();   // Hs visible + Bs1 ready

        // GEMM2: acc2 += Hs @ W2c
        gemm128(Hs, Bs1, acc2);
        __syncthreads();   // before next iter overwrites Hs / Bs1
    }

    // final epilogue: + b2 + rst
    #pragma unroll
    for (int mi = 0; mi < 2; mi++) {
        #pragma unroll
        for (int half = 0; half < 2; half++) {
            int row = m_off + mi * 16 + (lane >> 2) + half * 8;
            int gr = r0 + row;
            if (gr >= M) continue;
            #pragma unroll
            for (int ni = 0; ni < 8; ni++) {
                int col = n_off + ni * 8 + (lane & 3) * 2;
                float v0 = acc2[mi][ni][half * 2 + 0] + b2[col] + rst[(long)gr * D + col];
                float v1 = acc2[mi][ni][half * 2 + 1] + b2[col + 1] + rst[(long)gr * D + col + 1];
                st2(out + (long)gr * D + col, v0, v1);
            }
        }
    }
}

// ---------------- fused attention + hop1 (warp per dst node) ----------------
__global__ void attn_hop1_kernel(const int* __restrict__ rowoff, const int* __restrict__ deg,
                                 const int* __restrict__ pk,
                                 const __half* __restrict__ kqv,
                                 const float* __restrict__ relp, __half* __restrict__ exh,
                                 float* __restrict__ nscale, __half* __restrict__ fA, int N) {
    int w = (blockIdx.x * blockDim.x + threadIdx.x) >> 5;
    if (w >= N) return;
    int lane = threadIdx.x & 31;
    int head4 = lane >> 2;
    int start = rowoff[w];
    int dg = deg[w];
    float4 q4 = ld4(kqv + (long)w * 384 + 128 + lane * 4);
    float c = log1pf((float)dg) * 0.25f;  // log_in / sqrt(DH)
    float sum = 0.0f;
    float4 acc = make_float4(0.f, 0.f, 0.f, 0.f);
    int i = 0;
    for (; i + 2 <= dg; i += 2) {
        int pk0 = pk[start + i], pk1 = pk[start + i + 1];
        long s0 = (long)(pk0 & SRCMASK) * 384, s1 = (long)(pk1 & SRCMASK) * 384;
        float4 k0 = ld4(kqv + s0 + lane * 4);
        float4 k1 = ld4(kqv + s1 + lane * 4);
        float4 r0 = ld4(relp + (long)(pk0 >> 20) * D + lane * 4);
        float4 r1 = ld4(relp + (long)(pk1 >> 20) * D + lane * 4);
        float p0 = k0.x * r0.x * q4.x + k0.y * r0.y * q4.y + k0.z * r0.z * q4.z + k0.w * r0.w * q4.w;
        float p1 = k1.x * r1.x * q4.x + k1.y * r1.y * q4.y + k1.z * r1.z * q4.z + k1.w * r1.w * q4.w;
        p0 += __shfl_xor_sync(0xffffffffu, p0, 1);
        p1 += __shfl_xor_sync(0xffffffffu, p1, 1);
        p0 += __shfl_xor_sync(0xffffffffu, p0, 2);
        p1 += __shfl_xor_sync(0xffffffffu, p1, 2);
        float e0 = __expf(p0 * c);   // logits tiny: no max-subtraction needed
        float e1 = __expf(p1 * c);
        if ((lane & 3) == 0) {
            exh[(long)(start + i) * H + head4] = __float2half(e0);
            exh[(long)(start + i + 1) * H + head4] = __float2half(e1);
        }
        float4 v0 = ld4(kqv + s0 + 256 + lane * 4);
        float4 v1 = ld4(kqv + s1 + 256 + lane * 4);
        acc.x += e0 * v0.x + e1 * v1.x;
        acc.y += e0 * v0.y + e1 * v1.y;
        acc.z += e0 * v0.z + e1 * v1.z;
        acc.w += e0 * v0.w + e1 * v1.w;
        sum += e0 + e1;
    }
    if (i < dg) {
        int pk0 = pk[start + i];
        long s0 = (long)(pk0 & SRCMASK) * 384;
        float4 k0 = ld4(kqv + s0 + lane * 4);
        float4 r0 = ld4(relp + (long)(pk0 >> 20) * D + lane * 4);
        float p0 = k0.x * r0.x * q4.x + k0.y * r0.y * q4.y + k0.z * r0.z * q4.z + k0.w * r0.w * q4.w;
        p0 += __shfl_xor_sync(0xffffffffu, p0, 1);
        p0 += __shfl_xor_sync(0xffffffffu, p0, 2);
        float e0 = __expf(p0 * c);
        if ((lane & 3) == 0) exh[(long)(start + i) * H + head4] = __float2half(e0);
        float4 v0 = ld4(kqv + s0 + 256 + lane * 4);
        acc.x += e0 * v0.x;
        acc.y += e0 * v0.y;
        acc.z += e0 * v0.z;
        acc.w += e0 * v0.w;
        sum += e0;
    }
    // per-head sum lives replicated in each quad after the 2-shfl reduce? No:
    // sum accumulated e for the head of this lane's quad -> all 4 lanes of a
    // quad hold the same sum (e was quad-uniform). Scale directly.
    float sc = (sum > 0.0f) ? ((1.0f - ALPHA) / sum) : 0.0f;
    float4 z = ld4(kqv + (long)w * 384 + 256 + lane * 4);
    acc.x = acc.x * sc + ALPHA * z.x;
    acc.y = acc.y * sc + ALPHA * z.y;
    acc.z = acc.z * sc + ALPHA * z.z;
    acc.w = acc.w * sc + ALPHA * z.w;
    float2 pkd;
    ((__half2*)&pkd)[0] = __floats2half2_rn(acc.x, acc.y);
    ((__half2*)&pkd)[1] = __floats2half2_rn(acc.z, acc.w);
    *(float2*)(fA + (long)w * D + lane * 4) = pkd;
    float s_h = __shfl_sync(0xffffffffu, sum, (lane & 7) * 4);
    if (lane < 8)
        nscale[(long)w * H + lane] = (s_h > 0.0f) ? ((1.0f - ALPHA) / s_h) : 0.0f;
}

// ---------------- PPR diffusion hop (warp per dst node, unroll-2) ----------------
__global__ void hop_kernel(const int* __restrict__ rowoff, const int* __restrict__ deg,
                           const int* __restrict__ pk, const __half* __restrict__ exh,
                           const float* __restrict__ nscale,
                           const __half* __restrict__ fin,
                           const __half* __restrict__ f0,
                           __half* __restrict__ fout, int N) {
    int w = (blockIdx.x * blockDim.x + threadIdx.x) >> 5;
    if (w >= N) return;
    int lane = threadIdx.x & 31;
    int head = lane >> 2;
    int start = rowoff[w];
    int dg = deg[w];
    float4 acc = make_float4(0.f, 0.f, 0.f, 0.f);
    int i = 0;
    for (; i + 2 <= dg; i += 2) {
        int pk0 = pk[start + i], pk1 = pk[start + i + 1];
        float e0 = __half2float(exh[(long)(start + i) * H + head]);
        float e1 = __half2float(exh[(long)(start + i + 1) * H + head]);
        float4 fa = ld4(fin + (long)(pk0 & SRCMASK) * D + lane * 4);
        float4 fb = ld4(fin + (long)(pk1 & SRCMASK) * D + lane * 4);
        acc.x += e0 * fa.x + e1 * fb.x;
        acc.y += e0 * fa.y + e1 * fb.y;
        acc.z += e0 * fa.z + e1 * fb.z;
        acc.w += e0 * fa.w + e1 * fb.w;
    }
    if (i < dg) {
        int pk0 = pk[start + i];
        float e0 = __half2float(exh[(long)(start + i) * H + head]);
        float4 fa = ld4(fin + (long)(pk0 & SRCMASK) * D + lane * 4);
        acc.x += e0 * fa.x;
        acc.y += e0 * fa.y;
        acc.z += e0 * fa.z;
        acc.w += e0 * fa.w;
    }
    float sc = nscale[(long)w * H + head];
    float4 z = ld4(f0 + (long)w * 384 + lane * 4);   // v inside kqv
    acc.x = acc.x * sc + ALPHA * z.x;
    acc.y = acc.y * sc + ALPHA * z.y;
    acc.z = acc.z * sc + ALPHA * z.z;
    acc.w = acc.w * sc + ALPHA * z.w;
    float2 pkd;
    ((__half2*)&pkd)[0] = __floats2half2_rn(acc.x, acc.y);
    ((__half2*)&pkd)[1] = __floats2half2_rn(acc.z, acc.w);
    *(float2*)(fout + (long)w * D + lane * 4) = pkd;
}

// ---------------- last hop fused with residual + LN ----------------
__global__ void hop_last_kernel(const int* __restrict__ rowoff, const int* __restrict__ deg,
                                const int* __restrict__ pk, const __half* __restrict__ exh,
                                const float* __restrict__ nscale,
                                const __half* __restrict__ fin, const __half* __restrict__ f0,
                                const float* __restrict__ ent,
                                const float* __restrict__ g, const float* __restrict__ b,
                                __half* __restrict__ y, float* __restrict__ rst, int N) {
    int w = (blockIdx.x * blockDim.x + threadIdx.x) >> 5;
    if (w >= N) return;
    int lane = threadIdx.x & 31;
    int head = lane >> 2;
    int start = rowoff[w];
    int dg = deg[w];
    float4 acc = make_float4(0.f, 0.f, 0.f, 0.f);
    int i = 0;
    for (; i + 2 <= dg; i += 2) {
        int pk0 = pk[start + i], pk1 = pk[start + i + 1];
        float e0 = __half2float(exh[(long)(start + i) * H + head]);
        float e1 = __half2float(exh[(long)(start + i + 1) * H + head]);
        float4 fa = ld4(fin + (long)(pk0 & SRCMASK) * D + lane * 4);
        float4 fb = ld4(fin + (long)(pk1 & SRCMASK) * D + lane * 4);
        acc.x += e0 * fa.x + e1 * fb.x;
        acc.y += e0 * fa.y + e1 * fb.y;
        acc.z += e0 * fa.z + e1 * fb.z;
        acc.w += e0 * fa.w + e1 * fb.w;
    }
    if (i < dg) {
        int pk0 = pk[start + i];
        float e0 = __half2float(exh[(long)(start + i) * H + head]);
        float4 fa = ld4(fin + (long)(pk0 & SRCMASK) * D + lane * 4);
        acc.x += e0 * fa.x;
        acc.y += e0 * fa.y;
        acc.z += e0 * fa.z;
        acc.w += e0 * fa.w;
    }
    float sc = nscale[(long)w * H + head];
    float4 z = ld4(f0 + (long)w * 384 + lane * 4);
    float4 e4 = *(const float4*)(ent + (long)w * D + lane * 4);
    float4 v;
    v.x = acc.x * sc + ALPHA * z.x + e4.x;
    v.y = acc.y * sc + ALPHA * z.y + e4.y;
    v.z = acc.z * sc + ALPHA * z.z + e4.z;
    v.w = acc.w * sc + ALPHA * z.w + e4.w;
    *(float4*)(rst + (long)w * D + lane * 4) = v;
    float s = v.x + v.y + v.z + v.w;
    #pragma unroll
    for (int o = 16; o; o >>= 1) s += __shfl_xor_sync(0xffffffffu, s, o);
    float mean = s * (1.0f / 128.0f);
    float dx = v.x - mean, dy = v.y - mean, dz = v.z - mean, dw = v.w - mean;
    float q = dx * dx + dy * dy + dz * dz + dw * dw;
    #pragma unroll
    for (int o = 16; o; o >>= 1) q += __shfl_xor_sync(0xffffffffu, q, o);
    float inv = rsqrtf(q * (1.0f / 128.0f) + 1e-5f);
    float4 g4 = *(const float4*)(g + lane * 4);
    float4 b4 = *(const float4*)(b + lane * 4);
    st2(y + (long)w * D + lane * 4,     dx * inv * g4.x + b4.x, dy * inv * g4.y + b4.y);
    st2(y + (long)w * D + lane * 4 + 2, dz * inv * g4.z + b4.z, dw * inv * g4.w + b4.w);
}

// ---------------- launch ----------------
extern "C" void kernel_launch(void* const* d_in, const int* in_sizes, int n_in,
                              void* d_out, int out_size) {
    const float* ent    = (const float*)d_in[0];
    const float* relf   = (const float*)d_in[1];
    const float* W_head = (const float*)d_in[2];
    const float* W_tail = (const float*)d_in[3];
    const float* W_ent  = (const float*)d_in[4];
    const float* W_rel  = (const float*)d_in[5];
    const float* g_ent  = (const float*)d_in[6];
    const float* b_ent  = (const float*)d_in[7];
    const float* g_rel  = (const float*)d_in[8];
    const float* b_rel  = (const float*)d_in[9];
    const float* g_ff   = (const float*)d_in[10];
    const float* b_ff   = (const float*)d_in[11];
    const float* W1     = (const float*)d_in[12];
    const float* b1     = (const float*)d_in[13];
    const float* W2     = (const float*)d_in[14];
    const float* b2     = (const float*)d_in[15];
    const int*   src    = (const int*)d_in[16];
    const int*   dst    = (const int*)d_in[17];
    const int*   rid    = (const int*)d_in[18];
    float* out = (float*)d_out;

    int N = in_sizes[0] / D;
    int R = in_sizes[1] / D;
    int E = in_sizes[16];

    float *p_rst, *p_nscale, *p_relp;
    __half *p_xnh, *p_kqv, *p_fA, *p_fB, *p_exh, *p_relxh, *p_w16;
    int *p_deg, *p_rowoff, *p_cursor, *p_pk, *p_bsums;
    cudaGetSymbolAddress((void**)&p_xnh, d_xnh);
    cudaGetSymbolAddress((void**)&p_kqv, d_kqv);
    cudaGetSymbolAddress((void**)&p_rst, d_rst);
    cudaGetSymbolAddress((void**)&p_fA, d_fA);
    cudaGetSymbolAddress((void**)&p_fB, d_fB);
    cudaGetSymbolAddress((void**)&p_exh, d_exh);
    cudaGetSymbolAddress((void**)&p_nscale, d_nscale);
    cudaGetSymbolAddress((void**)&p_relxh, d_relxh);
    cudaGetSymbolAddress((void**)&p_relp, d_relp);
    cudaGetSymbolAddress((void**)&p_w16, d_w16);
    cudaGetSymbolAddress((void**)&p_deg, d_deg);
    cudaGetSymbolAddress((void**)&p_rowoff, d_rowoff);
    cudaGetSymbolAddress((void**)&p_cursor, d_cursor);
    cudaGetSymbolAddress((void**)&p_pk, d_pk);
    cudaGetSymbolAddress((void**)&p_bsums, d_bsums);

    cudaFuncSetAttribute(ffn_fused_kernel,
                         cudaFuncAttributeMaxDynamicSharedMemorySize, FFN_SMEM);

    int nb = (N + 1023) / 1024;
    int mblocks = (N + 127) / 128;

    // ordered so launch idx 5 (ncu -s 5 -c 1) is the big fused kqv GEMM
    cvt_weights<<<192, 256>>>(W_head, W_tail, W_ent, W_rel, W1, W2, p_w16);   // 0
    ln_kernel<__half><<<(N + 7) / 8, 256>>>(ent, g_ent, b_ent, p_xnh, N);     // 1
    zero_deg_kernel<<<(N + 255) / 256, 256>>>(p_deg, N);                      // 2
    hist_kernel<<<(E + 255) / 256, 256>>>(dst, p_deg, E);                     // 3
    scan1_kernel<<<nb, 1024>>>(p_deg, p_rowoff, p_bsums, N);                  // 4
    mm_f16_kernel<0, __half><<<dim3(mblocks, 3), 256>>>(                      // 5 <- profiled
        p_xnh, p_w16 + OFF_WKQV, nullptr, nullptr, p_kqv, N, 128, 384);
    scan2_kernel<<<1, 256>>>(p_bsums, nb);
    scan3_kernel<<<(N + 255) / 256, 256>>>(p_rowoff, p_cursor, p_bsums, N);
    scatter_kernel<<<(E + 255) / 256, 256>>>(src, dst, rid, p_cursor, p_pk, E);
    ln_kernel<__half><<<(R + 7) / 8, 256>>>(relf, g_rel, b_rel, p_relxh, R);
    mm_f16_kernel<0, float><<<dim3(1, 1), 256>>>(
        p_relxh, p_w16 + OFF_WR, nullptr, nullptr, p_relp, R, 128, 128);

    // fused attention + hop1
    attn_hop1_kernel<<<(N + 7) / 8, 256>>>(p_rowoff, p_deg, p_pk, p_kqv,
                                           p_relp, p_exh, p_nscale, p_fA, N);

    // hops 2,3 then last fused with residual+LN
    hop_kernel<<<(N + 7) / 8, 256>>>(p_rowoff, p_deg, p_pk, p_exh, p_nscale,
                                     p_fA, p_kqv + 256, p_fB, N);
    hop_kernel<<<(N + 7) / 8, 256>>>(p_rowoff, p_deg, p_pk, p_exh, p_nscale,
                                     p_fB, p_kqv + 256, p_fA, N);
    hop_last_kernel<<<(N + 7) / 8, 256>>>(p_rowoff, p_deg, p_pk, p_exh, p_nscale,
                                          p_fA, p_kqv + 256, ent, g_ff, b_ff,
                                          p_xnh, p_rst, N);   // y -> d_xnh

    // fused FFN
    ffn_fused_kernel<<<mblocks, 256, FFN_SMEM>>>(
        p_xnh, p_w16 + OFF_W1, p_w16 + OFF_W2, b1, b2, p_rst, out, N);
}